// round 14
// baseline (speedup 1.0000x reference)
#include <cuda_runtime.h>
#include <cuda_bf16.h>
#include <cuda_fp16.h>
#include <cstdint>
#include <math.h>

#define BB 4
#define SS 1024
#define EE 512
#define HH 512
#define VV 32000
#define MM (BB*SS)      // 4096
#define NH 8
#define DH 64

// ---------------- scratch (static device memory; no allocations) ----------------
__device__ float g_I[MM*HH];
__device__ float g_s[MM*HH];
__device__ float g_qkv[MM*3*HH];
__device__ __half g_Ahi[MM*HH],  g_Alo[MM*HH];    // activation fp16 hi/lo
__device__ __half g_A2hi[MM*HH], g_A2lo[MM*HH];   // attention-out fp16 hi/lo
__device__ __half g_H2[MM*HH];                    // h2 fp16 (vocab A)
__device__ __half g_W0h[HH*EE];
__device__ __half g_W1h[HH*HH];
__device__ __half g_Wqh[3*HH*HH];
__device__ __half g_Woh[HH*HH];
__device__ __half g_Bh[(size_t)VV*HH];            // vocab weights fp16
__device__ __half g_Qh[32*1024*64];               // Q fp16 [bh][s][d]
__device__ __half g_Kh[32*1024*64];               // K fp16 [bh][s][d]
__device__ __half g_Vth[32*64*1024];              // V fp16 transposed [bh][d][k]

__device__ __forceinline__ uint32_t smem_u32(const void* p) {
    uint32_t a;
    asm("{ .reg .u64 t; cvta.to.shared.u64 t, %1; cvt.u32.u64 %0, t; }" : "=r"(a) : "l"(p));
    return a;
}
__device__ __forceinline__ void cp_async16(uint32_t dst, const void* src) {
    asm volatile("cp.async.cg.shared.global [%0], [%1], 16;" :: "r"(dst), "l"(src));
}
__device__ __forceinline__ void ldsm_x4(uint32_t& r0, uint32_t& r1, uint32_t& r2, uint32_t& r3,
                                        uint32_t addr) {
    asm volatile("ldmatrix.sync.aligned.m8n8.x4.shared.b16 {%0,%1,%2,%3}, [%4];"
                 : "=r"(r0), "=r"(r1), "=r"(r2), "=r"(r3) : "r"(addr));
}
__device__ __forceinline__ void mma_f16(float* c, const uint32_t* a, const uint32_t* b) {
    asm volatile("mma.sync.aligned.m16n8k16.row.col.f32.f16.f16.f32 "
                 "{%0,%1,%2,%3}, {%4,%5,%6,%7}, {%8,%9}, {%0,%1,%2,%3};"
                 : "+f"(c[0]), "+f"(c[1]), "+f"(c[2]), "+f"(c[3])
                 : "r"(a[0]), "r"(a[1]), "r"(a[2]), "r"(a[3]), "r"(b[0]), "r"(b[1]));
}
__device__ __forceinline__ uint32_t pack_h2(float a, float b) {
    __half2 h = __floats2half2_rn(a, b);
    return *(uint32_t*)&h;
}

// ---------------- merged preprocessing ----------------
#define N_VOC ((long long)VV*HH)
#define N_W0  (HH*EE)
#define N_W1  (HH*HH)
#define N_WQ  (3*HH*HH)
#define N_WO  (HH*HH)
#define N_EMB (MM*EE)
#define N_PREP (N_VOC + N_W0 + N_W1 + N_WQ + N_WO + N_EMB)

__global__ void prep_kernel(const float* __restrict__ out_w,
                            const float* __restrict__ W0,
                            const float* __restrict__ W1,
                            const float* __restrict__ Wq,
                            const float* __restrict__ Wo,
                            const int* __restrict__ x,
                            const float* __restrict__ emb) {
    long long idx = (long long)blockIdx.x * blockDim.x + threadIdx.x;
    if (idx < N_VOC) { g_Bh[idx] = __float2half(out_w[idx]); return; }
    idx -= N_VOC;
    if (idx < N_W0) { g_W0h[idx] = __float2half(W0[idx]); return; }
    idx -= N_W0;
    if (idx < N_W1) { g_W1h[idx] = __float2half(W1[idx]); return; }
    idx -= N_W1;
    if (idx < N_WQ) { g_Wqh[idx] = __float2half(Wq[idx]); return; }
    idx -= N_WQ;
    if (idx < N_WO) { g_Woh[idx] = __float2half(Wo[idx]); return; }
    idx -= N_WO;
    if (idx >= N_EMB) return;
    int i = (int)idx;
    int m = i >> 9;
    int e = i & 511;
    int s = m & (SS - 1);
    int tok = x[m];
    int i2 = e & ~1;
    float freq = expf((float)i2 * (-9.210340371976184f / 512.0f));
    float ang = (float)s * freq;
    float pe = (e & 1) ? cosf(ang) : sinf(ang);
    float v = emb[(size_t)tok * EE + e] + pe;
    __half h = __float2half(v);
    g_Ahi[i] = h;
    g_Alo[i] = __float2half(v - __half2float(h));
}

// ============== fp16 NT GEMM, 1- or 2-term A ==============
#define SPAD 40
#define TILE_E (128*SPAD)
#define GF_SMEM (2*3*TILE_E*2)    // 61440 bytes

__global__ __launch_bounds__(256, 2) void gemm_f16_mma(
    const __half* __restrict__ Ahi_, const __half* __restrict__ Alo_,
    const __half* __restrict__ B_,
    const float* __restrict__ bias, float* __restrict__ C_,
    __half* __restrict__ Chi_, __half* __restrict__ Clo_,
    __half* __restrict__ Fh_,
    int K, int lda, int ldb, int ldc, int nValid, float scale,
    int zmod, long long sA1, long long sA2, long long sB1, long long sB2,
    long long sC1, long long sC2)
{
    extern __shared__ __align__(16) __half smh[];
    const uint32_t smb = smem_u32(smh);

    const int tid = threadIdx.x;
    const int lane = tid & 31;
    const int wid = tid >> 5;
    const int warp_m = wid >> 2;
    const int warp_n = wid & 3;
    const int bm = blockIdx.y * 128;
    const int bn = blockIdx.x * 128;
    const bool two = (Alo_ != nullptr);

    const int z = blockIdx.z;
    const int z1 = z % zmod, z2 = z / zmod;
    const long long offA = (long long)z1 * sA1 + (long long)z2 * sA2;
    const long long offB = (long long)z1 * sB1 + (long long)z2 * sB2;
    const long long offC = (long long)z1 * sC1 + (long long)z2 * sC2;

    const __half* pT[3] = { Ahi_ + offA + (size_t)bm * lda,
                            two ? (Alo_ + offA + (size_t)bm * lda) : nullptr,
                            B_   + offB + (size_t)bn * ldb };

    float acc[4][4][4];
    #pragma unroll
    for (int i = 0; i < 4; i++)
        #pragma unroll
        for (int j = 0; j < 4; j++)
            #pragma unroll
            for (int r = 0; r < 4; r++) acc[i][j][r] = 0.f;

    const int lrow = tid >> 2;
    const int lcol = (tid & 3) * 8;
    const int nstages = K >> 5;

    auto prefetch = [&](int s) {
        const int gk = s * 32;
        const uint32_t base = smb + (uint32_t)((s & 1) * 3 * TILE_E) * 2;
        #pragma unroll
        for (int t = 0; t < 3; t++) {
            if (t == 1 && !two) continue;
            const __half* src = pT[t] + gk + lcol;
            const int ld = (t < 2) ? lda : ldb;
            #pragma unroll
            for (int c = 0; c < 2; c++) {
                int row = lrow + c * 64;
                cp_async16(base + (uint32_t)(t * TILE_E + row * SPAD + lcol) * 2,
                           src + (size_t)row * ld);
            }
        }
    };

    prefetch(0);
    asm volatile("cp.async.commit_group;");

    for (int s = 0; s < nstages; s++) {
        if (s < nstages - 1) {
            prefetch(s + 1);
            asm volatile("cp.async.commit_group;");
            asm volatile("cp.async.wait_group 1;");
        } else {
            asm volatile("cp.async.wait_group 0;");
        }
        __syncthreads();

        const uint32_t stg = smb + (uint32_t)((s & 1) * 3 * TILE_E) * 2;
        const uint32_t tAhi = stg;
        const uint32_t tAlo = stg + TILE_E * 2;
        const uint32_t tB   = stg + 2 * TILE_E * 2;
        const int q  = lane >> 3;
        const int rr = lane & 7;

        #pragma unroll
        for (int ko = 0; ko < 32; ko += 16) {
            const int arow = warp_m * 64 + (q & 1) * 8 + rr;
            const int acol = ko + (q >> 1) * 8;
            const int brow = warp_n * 32 + (q >> 1) * 8 + rr;
            const int bcol = ko + (q & 1) * 8;

            uint32_t b[4][2];
            #pragma unroll
            for (int j = 0; j < 2; j++)
                ldsm_x4(b[2*j][0], b[2*j][1], b[2*j+1][0], b[2*j+1][1],
                        tB + (uint32_t)((brow + j * 16) * SPAD + bcol) * 2);
            uint32_t aH[4][4];
            #pragma unroll
            for (int i = 0; i < 4; i++)
                ldsm_x4(aH[i][0], aH[i][1], aH[i][2], aH[i][3],
                        tAhi + (uint32_t)((arow + i * 16) * SPAD + acol) * 2);
            #pragma unroll
            for (int i = 0; i < 4; i++)
                #pragma unroll
                for (int j = 0; j < 4; j++)
                    mma_f16(acc[i][j], aH[i], b[j]);
            if (two) {
                uint32_t aL[4][4];
                #pragma unroll
                for (int i = 0; i < 4; i++)
                    ldsm_x4(aL[i][0], aL[i][1], aL[i][2], aL[i][3],
                            tAlo + (uint32_t)((arow + i * 16) * SPAD + acol) * 2);
                #pragma unroll
                for (int i = 0; i < 4; i++)
                    #pragma unroll
                    for (int j = 0; j < 4; j++)
                        mma_f16(acc[i][j], aL[i], b[j]);
            }
        }
        __syncthreads();
    }

    const int gr = lane >> 2;
    const int gc = (lane & 3) * 2;
    float* C = C_ ? C_ + offC : nullptr;
    __half* Chi = Chi_ ? Chi_ + offC : nullptr;
    __half* Clo = Clo_ ? Clo_ + offC : nullptr;
    __half* Fh = Fh_ ? Fh_ + offC : nullptr;

    #pragma unroll
    for (int j = 0; j < 4; j++) {
        int col = bn + warp_n * 32 + j * 8 + gc;
        if (col >= nValid) continue;
        float2 bv = make_float2(0.f, 0.f);
        if (bias) bv = *(const float2*)(bias + col);
        #pragma unroll
        for (int i = 0; i < 4; i++) {
            int row0 = bm + warp_m * 64 + i * 16 + gr;
            float v00 = acc[i][j][0]*scale + bv.x, v01 = acc[i][j][1]*scale + bv.y;
            float v10 = acc[i][j][2]*scale + bv.x, v11 = acc[i][j][3]*scale + bv.y;
            size_t o0 = (size_t)row0 * ldc + col;
            size_t o1 = (size_t)(row0 + 8) * ldc + col;
            if (Chi) {
                __half h;
                h = __float2half(v00); Chi[o0]   = h; Clo[o0]   = __float2half(v00 - __half2float(h));
                h = __float2half(v01); Chi[o0+1] = h; Clo[o0+1] = __float2half(v01 - __half2float(h));
                h = __float2half(v10); Chi[o1]   = h; Clo[o1]   = __float2half(v10 - __half2float(h));
                h = __float2half(v11); Chi[o1+1] = h; Clo[o1+1] = __float2half(v11 - __half2float(h));
            } else if (Fh) {
                *(__half2*)(Fh + o0) = __floats2half2_rn(v00, v01);
                *(__half2*)(Fh + o1) = __floats2half2_rn(v10, v11);
            } else {
                *(float2*)(C + o0) = make_float2(v00, v01);
                *(float2*)(C + o1) = make_float2(v10, v11);
            }
        }
    }
}

// ============== fused flash attention ==============
// Per block: one (bh, 128-q tile). Loop over 8 k-chunks of 128.
// S = Q@K^T (fp32 acc), P = exp(S/8) (no max shift; logits ~N(0,1), clamped),
// O += P@V, denom l accumulated; epilogue normalizes and writes fp16 hi/lo.
#define FA_QSTR 72
#define FA_VSTR 136
#define FA_OFF_K 18432u                 // Q: 128*72*2 = 18432
#define FA_KBUF  18432u                 // K buf: 128*72*2
#define FA_OFF_V (18432u + 36864u)      // 55296
#define FA_VBUF  17408u                 // Vt buf: 64*136*2
#define FA_OFF_L (55296u + 34816u)      // 90112
#define FA_SMEM  (90112 + 512)          // 90624 bytes
#define FA_OSTR  68                     // Obuf float stride (reuses K region)

__global__ __launch_bounds__(256, 1) void flash_attn_kernel(
    const __half* __restrict__ Qg_, const __half* __restrict__ Kg_,
    const __half* __restrict__ Vg_,
    __half* __restrict__ A2hi, __half* __restrict__ A2lo)
{
    extern __shared__ __align__(16) char sm[];
    const uint32_t smb = smem_u32(sm);
    const int tid = threadIdx.x;
    const int lane = tid & 31;
    const int wid = tid >> 5;
    const int warp_m = wid >> 1;      // 0..3 (32 q rows each)
    const int warp_n = wid & 1;       // 0..1 (64 k cols each)
    const int q0 = blockIdx.x * 128;
    const int bh = blockIdx.y;
    const int b = bh >> 3, h = bh & 7;

    const __half* Qg = Qg_ + (size_t)bh * 65536 + (size_t)q0 * 64;
    const __half* Kg = Kg_ + (size_t)bh * 65536;
    const __half* Vg = Vg_ + (size_t)bh * 65536;   // [d][k] 64x1024

    // Q load (once): [128 q][64 d] -> smem stride 72
    #pragma unroll
    for (int t = 0; t < 4; t++) {
        int u = tid + t * 256;
        int r = u >> 3, c8 = u & 7;
        cp_async16(smb + (uint32_t)(r * FA_QSTR + c8 * 8) * 2, Qg + (size_t)r * 64 + c8 * 8);
    }

    auto prefetch = [&](int kt) {
        int buf = kt & 1;
        const __half* Kc = Kg + (size_t)kt * 128 * 64;
        #pragma unroll
        for (int t = 0; t < 4; t++) {
            int u = tid + t * 256;
            int r = u >> 3, c8 = u & 7;
            cp_async16(smb + FA_OFF_K + buf * FA_KBUF + (uint32_t)(r * FA_QSTR + c8 * 8) * 2,
                       Kc + (size_t)r * 64 + c8 * 8);
        }
        const __half* Vc = Vg + kt * 128;
        #pragma unroll
        for (int t = 0; t < 4; t++) {
            int u = tid + t * 256;
            int r = u >> 4, c8 = u & 15;
            cp_async16(smb + FA_OFF_V + buf * FA_VBUF + (uint32_t)(r * FA_VSTR + c8 * 8) * 2,
                       Vc + (size_t)r * 1024 + c8 * 8);
        }
    };
    prefetch(0);
    asm volatile("cp.async.commit_group;");

    float oacc[2][8][4];
    #pragma unroll
    for (int i = 0; i < 2; i++)
        #pragma unroll
        for (int j = 0; j < 8; j++)
            #pragma unroll
            for (int r = 0; r < 4; r++) oacc[i][j][r] = 0.f;
    float lsum[2][2] = {{0.f, 0.f}, {0.f, 0.f}};

    const int qq = lane >> 3;   // 0..3
    const int rr = lane & 7;    // 0..7

    for (int kt = 0; kt < 8; kt++) {
        if (kt < 7) {
            prefetch(kt + 1);
            asm volatile("cp.async.commit_group;");
            asm volatile("cp.async.wait_group 1;");
        } else {
            asm volatile("cp.async.wait_group 0;");
        }
        __syncthreads();

        const uint32_t bK = smb + FA_OFF_K + (uint32_t)((kt & 1) * FA_KBUF);
        const uint32_t bV = smb + FA_OFF_V + (uint32_t)((kt & 1) * FA_VBUF);

        // ---- S = Q @ K^T : warp tile 32q x 64k ----
        float sacc[2][8][4];
        #pragma unroll
        for (int i = 0; i < 2; i++)
            #pragma unroll
            for (int j = 0; j < 8; j++)
                #pragma unroll
                for (int r = 0; r < 4; r++) sacc[i][j][r] = 0.f;

        #pragma unroll
        for (int ko = 0; ko < 64; ko += 16) {
            uint32_t a[2][4];
            #pragma unroll
            for (int i = 0; i < 2; i++) {
                int arow = warp_m * 32 + i * 16 + (qq & 1) * 8 + rr;
                int acol = ko + (qq >> 1) * 8;
                ldsm_x4(a[i][0], a[i][1], a[i][2], a[i][3],
                        smb + (uint32_t)(arow * FA_QSTR + acol) * 2);
            }
            uint32_t bf[8][2];
            #pragma unroll
            for (int j16 = 0; j16 < 4; j16++) {
                int brow = warp_n * 64 + j16 * 16 + (qq >> 1) * 8 + rr;
                int bcol = ko + (qq & 1) * 8;
                ldsm_x4(bf[2*j16][0], bf[2*j16][1], bf[2*j16+1][0], bf[2*j16+1][1],
                        bK + (uint32_t)(brow * FA_QSTR + bcol) * 2);
            }
            #pragma unroll
            for (int i = 0; i < 2; i++)
                #pragma unroll
                for (int j = 0; j < 8; j++)
                    mma_f16(sacc[i][j], a[i], bf[j]);
        }

        // ---- P = exp(S/8) in place; accumulate row sums ----
        #pragma unroll
        for (int i = 0; i < 2; i++)
            #pragma unroll
            for (int j = 0; j < 8; j++) {
                float e0 = __expf(fminf(sacc[i][j][0] * 0.125f, 10.5f));
                float e1 = __expf(fminf(sacc[i][j][1] * 0.125f, 10.5f));
                float e2 = __expf(fminf(sacc[i][j][2] * 0.125f, 10.5f));
                float e3 = __expf(fminf(sacc[i][j][3] * 0.125f, 10.5f));
                sacc[i][j][0] = e0; sacc[i][j][1] = e1;
                sacc[i][j][2] = e2; sacc[i][j][3] = e3;
                lsum[i][0] += e0 + e1;
                lsum[i][1] += e2 + e3;
            }

        // ---- O += P @ V : contraction over this warp's 64 k ----
        #pragma unroll
        for (int j16 = 0; j16 < 4; j16++) {
            uint32_t bv[8][2];
            #pragma unroll
            for (int nj = 0; nj < 4; nj++) {
                int brow = nj * 16 + (qq >> 1) * 8 + rr;                 // d
                int bcol = warp_n * 64 + j16 * 16 + (qq & 1) * 8;        // k
                ldsm_x4(bv[2*nj][0], bv[2*nj][1], bv[2*nj+1][0], bv[2*nj+1][1],
                        bV + (uint32_t)(brow * FA_VSTR + bcol) * 2);
            }
            #pragma unroll
            for (int i = 0; i < 2; i++) {
                uint32_t pa[4];
                pa[0] = pack_h2(sacc[i][2*j16][0],   sacc[i][2*j16][1]);
                pa[1] = pack_h2(sacc[i][2*j16][2],   sacc[i][2*j16][3]);
                pa[2] = pack_h2(sacc[i][2*j16+1][0], sacc[i][2*j16+1][1]);
                pa[3] = pack_h2(sacc[i][2*j16+1][2], sacc[i][2*j16+1][3]);
                #pragma unroll
                for (int nj = 0; nj < 8; nj++)
                    mma_f16(oacc[i][nj], pa, bv[nj]);
            }
        }
        __syncthreads();
    }

    // ---- epilogue: reduce l across lanes + warp_n; combine O partials ----
    float* l_sm = (float*)(sm + FA_OFF_L);
    float* Obuf = (float*)(sm + FA_OFF_K);   // reuse K region: 128 x 68 fp32

    #pragma unroll
    for (int i = 0; i < 2; i++)
        #pragma unroll
        for (int hh = 0; hh < 2; hh++) {
            float v = lsum[i][hh];
            v += __shfl_xor_sync(0xffffffffu, v, 1);
            v += __shfl_xor_sync(0xffffffffu, v, 2);
            lsum[i][hh] = v;
        }

    // phase 1: warp_n == 0 writes l and O
    if (warp_n == 0) {
        if ((lane & 3) == 0) {
            #pragma unroll
            for (int i = 0; i < 2; i++)
                #pragma unroll
                for (int hh = 0; hh < 2; hh++)
                    l_sm[warp_m*32 + i*16 + hh*8 + (lane >> 2)] = lsum[i][hh];
        }
        #pragma unroll
        for (int i = 0; i < 2; i++)
            #pragma unroll
            for (int j = 0; j < 8; j++) {
                int r0 = warp_m*32 + i*16 + (lane >> 2);
                int c0 = j*8 + (lane & 3)*2;
                Obuf[r0*FA_OSTR + c0]       = oacc[i][j][0];
                Obuf[r0*FA_OSTR + c0 + 1]   = oacc[i][j][1];
                Obuf[(r0+8)*FA_OSTR + c0]   = oacc[i][j][2];
                Obuf[(r0+8)*FA_OSTR + c0+1] = oacc[i][j][3];
            }
    }
    __syncthreads();
    // phase 2: warp_n == 1 accumulates
    if (warp_n == 1) {
        if ((lane & 3) == 0) {
            #pragma unroll
            for (int i = 0; i < 2; i++)
                #pragma unroll
                for (int hh = 0; hh < 2; hh++)
                    l_sm[warp_m*32 + i*16 + hh*8 + (lane >> 2)] += lsum[i][hh];
        }
        #pragma unroll
        for (int i = 0; i < 2; i++)
            #pragma unroll
            for (int j = 0; j < 8; j++) {
                int r0 = warp_m*32 + i*16 + (lane >> 2);
                int c0 = j*8 + (lane & 3)*2;
                Obuf[r0*FA_OSTR + c0]       += oacc[i][j][0];
                Obuf[r0*FA_OSTR + c0 + 1]   += oacc[i][j][1];
                Obuf[(r0+8)*FA_OSTR + c0]   += oacc[i][j][2];
                Obuf[(r0+8)*FA_OSTR + c0+1] += oacc[i][j][3];
            }
    }
    __syncthreads();

    // ---- normalize + write fp16 hi/lo to A2 ----
    {
        int row = tid >> 1;
        int cb  = (tid & 1) * 32;
        float inv = 1.f / l_sm[row];
        size_t gbase = ((size_t)(b * 1024 + q0 + row)) * 512 + h * 64 + cb;
        #pragma unroll
        for (int c = 0; c < 32; c += 2) {
            float v0 = Obuf[row*FA_OSTR + cb + c]     * inv;
            float v1 = Obuf[row*FA_OSTR + cb + c + 1] * inv;
            __half h0 = __float2half(v0);
            __half h1 = __float2half(v1);
            __half2 hi2; hi2.x = h0; hi2.y = h1;
            __half2 lo2;
            lo2.x = __float2half(v0 - __half2float(h0));
            lo2.y = __float2half(v1 - __half2float(h1));
            *(__half2*)(A2hi + gbase + c) = hi2;
            *(__half2*)(A2lo + gbase + c) = lo2;
        }
    }
}

// ---------------- parallel liquid scan (exact affine chunk decomposition) ----------------
__global__ __launch_bounds__(512) void liquid_scan_par(
    const float* __restrict__ I, const float* __restrict__ tau,
    const float* __restrict__ log_dt, float* __restrict__ out) {
    const int b = blockIdx.x;
    const int lg = blockIdx.y;
    const int lane16 = threadIdx.x & 15;
    const int chunk  = threadIdx.x >> 4;
    const int o = lg * 16 + lane16;
    const float dt = expf(log_dt[0]);
    const float r = dt / tau[o];
    const float a = 1.f - r;
    const float* Ib = I + (size_t)b * SS * HH + o;
    const int t0 = chunk * 32;

    float Iv[32];
    #pragma unroll
    for (int i = 0; i < 32; i++) Iv[i] = Ib[(size_t)(t0 + i) * HH];

    float u = 0.f, s = 0.f;
    #pragma unroll
    for (int i = 0; i < 32; i++) {
        float sn = s + r * (u - s);
        u = u + r * (Iv[i] - u);
        s = sn;
    }
    __shared__ float2 dloc[32][16];
    __shared__ float2 st[32][16];
    dloc[chunk][lane16] = make_float2(u, s);
    __syncthreads();

    if (chunk == 0) {
        float a2 = a*a, a4 = a2*a2, a8 = a4*a4, a16 = a8*a8;
        float a32v = a16*a16;
        float a31 = a16*a8*a4*a2*a;
        float c32 = 32.f * r * a31;
        float2 x = make_float2(0.f, 0.f);
        #pragma unroll
        for (int c = 0; c < 32; c++) {
            st[c][lane16] = x;
            float2 d = dloc[c][lane16];
            float nu = a32v * x.x + d.x;
            float ns = c32 * x.x + a32v * x.y + d.y;
            x = make_float2(nu, ns);
        }
    }
    __syncthreads();

    float2 x0 = st[chunk][lane16];
    u = x0.x; s = x0.y;
    float* Ob = out + (size_t)b * SS * HH + o;
    #pragma unroll
    for (int i = 0; i < 32; i++) {
        float sn = s + r * (u - s);
        u = u + r * (Iv[i] - u);
        s = sn;
        Ob[(size_t)(t0 + i) * HH] = tanhf(s);
    }
}

// ---------------- layernorm -> fp16 hi/lo ----------------
__global__ void layernorm_split(const float* __restrict__ in, const float* __restrict__ g,
                                const float* __restrict__ be,
                                __half* __restrict__ hi, __half* __restrict__ lo) {
    int row = blockIdx.x;
    int tid = threadIdx.x;
    const float* p = in + (size_t)row * HH;
    float a = p[tid], b = p[tid + 256];
    float sum = a + b, sq = a*a + b*b;
    __shared__ float s1[8], s2[8];
    #pragma unroll
    for (int o = 16; o; o >>= 1) {
        sum += __shfl_xor_sync(0xffffffffu, sum, o);
        sq  += __shfl_xor_sync(0xffffffffu, sq,  o);
    }
    if ((tid & 31) == 0) { s1[tid>>5] = sum; s2[tid>>5] = sq; }
    __syncthreads();
    sum = 0.f; sq = 0.f;
    #pragma unroll
    for (int i = 0; i < 8; i++) { sum += s1[i]; sq += s2[i]; }
    float mean = sum * (1.f/512.f);
    float var  = sq * (1.f/512.f) - mean*mean;
    float inv = rsqrtf(var + 1e-5f);
    float y0 = (a - mean) * inv * g[tid]       + be[tid];
    float y1 = (b - mean) * inv * g[tid + 256] + be[tid + 256];
    size_t base = (size_t)row * HH;
    __half h0 = __float2half(y0);
    __half h1 = __float2half(y1);
    hi[base + tid]       = h0;
    hi[base + tid + 256] = h1;
    lo[base + tid]       = __float2half(y0 - __half2float(h0));
    lo[base + tid + 256] = __float2half(y1 - __half2float(h1));
}

// ---------------- qkv split: Q/K fp16 [bh][s][d], V fp16 transposed [bh][d][k] ----------------
__global__ void qkv_split_kernel(const float* __restrict__ qkv) {
    int idx = blockIdx.x * blockDim.x + threadIdx.x;
    if (idx >= MM * 1536) return;
    int row = idx / 1536;
    int col = idx - row * 1536;
    int b = row >> 10, s = row & 1023;
    float v = qkv[idx];
    if (col < 512) {
        int hd = col >> 6, d = col & 63;
        g_Qh[((size_t)(b*8 + hd) * 1024 + s) * 64 + d] = __float2half(v);
    } else if (col < 1024) {
        int c = col - 512;
        int hd = c >> 6, d = c & 63;
        g_Kh[((size_t)(b*8 + hd) * 1024 + s) * 64 + d] = __float2half(v);
    } else {
        int c = col - 1024;
        int hd = c >> 6, d = c & 63;
        g_Vth[(size_t)(b*8 + hd) * 65536 + (size_t)d * 1024 + s] = __float2half(v);
    }
}

// ---------------- host orchestration ----------------
extern "C" void kernel_launch(void* const* d_in, const int* in_sizes, int n_in,
                              void* d_out, int out_size) {
    const int*   x          = (const int*)  d_in[0];
    const float* emb        = (const float*)d_in[1];
    const float* W0         = (const float*)d_in[2];
    const float* b0         = (const float*)d_in[3];
    const float* tau0       = (const float*)d_in[4];
    const float* g0         = (const float*)d_in[5];
    const float* be0        = (const float*)d_in[6];
    const float* W1         = (const float*)d_in[7];
    const float* b1         = (const float*)d_in[8];
    const float* tau1       = (const float*)d_in[9];
    const float* g1         = (const float*)d_in[10];
    const float* be1        = (const float*)d_in[11];
    const float* attn_in_w  = (const float*)d_in[12];
    const float* attn_in_b  = (const float*)d_in[13];
    const float* attn_out_w = (const float*)d_in[14];
    const float* attn_out_b = (const float*)d_in[15];
    const float* out_w      = (const float*)d_in[16];
    const float* out_b      = (const float*)d_in[17];
    const float* log_dt     = (const float*)d_in[18];
    float* out = (float*)d_out;

    float *I, *sbuf, *qkv;
    __half *Ahi, *Alo, *A2hi, *A2lo, *H2;
    __half *W0h, *W1h, *Wqh, *Woh, *Bh, *Qh, *Kh, *Vth;
    cudaGetSymbolAddress((void**)&I,      g_I);
    cudaGetSymbolAddress((void**)&sbuf,   g_s);
    cudaGetSymbolAddress((void**)&qkv,    g_qkv);
    cudaGetSymbolAddress((void**)&Ahi,    g_Ahi);
    cudaGetSymbolAddress((void**)&Alo,    g_Alo);
    cudaGetSymbolAddress((void**)&A2hi,   g_A2hi);
    cudaGetSymbolAddress((void**)&A2lo,   g_A2lo);
    cudaGetSymbolAddress((void**)&H2,     g_H2);
    cudaGetSymbolAddress((void**)&Bh,     g_Bh);
    cudaGetSymbolAddress((void**)&W0h,    g_W0h);
    cudaGetSymbolAddress((void**)&W1h,    g_W1h);
    cudaGetSymbolAddress((void**)&Wqh,    g_Wqh);
    cudaGetSymbolAddress((void**)&Woh,    g_Woh);
    cudaGetSymbolAddress((void**)&Qh,     g_Qh);
    cudaGetSymbolAddress((void**)&Kh,     g_Kh);
    cudaGetSymbolAddress((void**)&Vth,    g_Vth);

    cudaFuncSetAttribute(gemm_f16_mma,
                         cudaFuncAttributeMaxDynamicSharedMemorySize, GF_SMEM);
    cudaFuncSetAttribute(flash_attn_kernel,
                         cudaFuncAttributeMaxDynamicSharedMemorySize, FA_SMEM);

    // merged preprocessing: weight converts + embed+PE split (1 launch)
    prep_kernel<<<(unsigned)((N_PREP + 255)/256), 256>>>(out_w, W0, W1, attn_in_w, attn_out_w, x, emb);

    // 2. liquid layer 0 (fp16: exact A hi/lo x rounded W)
    gemm_f16_mma<<<dim3(4, 32, 1), 256, GF_SMEM>>>(
        Ahi, Alo, W0h, b0, I, nullptr, nullptr, nullptr,
        EE, EE, EE, HH, HH, 1.f, 1, 0,0,0,0,0,0);
    liquid_scan_par<<<dim3(BB, 32), 512>>>(I, tau0, log_dt, sbuf);
    layernorm_split<<<MM, 256>>>(sbuf, g0, be0, Ahi, Alo);

    // 3. liquid layer 1
    gemm_f16_mma<<<dim3(4, 32, 1), 256, GF_SMEM>>>(
        Ahi, Alo, W1h, b1, I, nullptr, nullptr, nullptr,
        HH, HH, HH, HH, HH, 1.f, 1, 0,0,0,0,0,0);
    liquid_scan_par<<<dim3(BB, 32), 512>>>(I, tau1, log_dt, sbuf);
    layernorm_split<<<MM, 256>>>(sbuf, g1, be1, Ahi, Alo);

    // 4. MHA: qkv projection (fp16 2-term A)
    gemm_f16_mma<<<dim3(12, 32, 1), 256, GF_SMEM>>>(
        Ahi, Alo, Wqh, attn_in_b, qkv, nullptr, nullptr, nullptr,
        HH, HH, HH, 3*HH, 3*HH, 1.f, 1, 0,0,0,0,0,0);
    qkv_split_kernel<<<(MM*1536 + 255)/256, 256>>>(qkv);

    // fused flash attention -> fp16 hi/lo A2
    flash_attn_kernel<<<dim3(8, 32), 256, FA_SMEM>>>(Qh, Kh, Vth, A2hi, A2lo);

    // out-projection (fp16 2-term A) -> single fp16 H2
    gemm_f16_mma<<<dim3(4, 32, 1), 256, GF_SMEM>>>(
        A2hi, A2lo, Woh, attn_out_b, nullptr, nullptr, nullptr, H2,
        HH, HH, HH, HH, HH, 1.f, 1, 0,0,0,0,0,0);

    // 5. vocab projection (fp16 1-term)
    gemm_f16_mma<<<dim3(VV/128, MM/128, 1), 256, GF_SMEM>>>(
        H2, nullptr, Bh, out_b, out, nullptr, nullptr, nullptr,
        HH, HH, HH, VV, VV, 1.f, 1, 0,0,0,0,0,0);
}

// round 15
// speedup vs baseline: 1.4362x; 1.4362x over previous
#include <cuda_runtime.h>
#include <cuda_bf16.h>
#include <cuda_fp16.h>
#include <cstdint>
#include <math.h>

#define BB 4
#define SS 1024
#define EE 512
#define HH 512
#define VV 32000
#define MM (BB*SS)      // 4096
#define NH 8
#define DH 64

// ---------------- scratch (static device memory; no allocations) ----------------
__device__ float g_I[MM*HH];
__device__ float g_s[MM*HH];
__device__ float g_qkv[MM*3*HH];
__device__ float g_l[32*1024];                    // attention row sums (atomic)
__device__ __half g_Ahi[MM*HH],  g_Alo[MM*HH];    // activation fp16 hi/lo
__device__ __half g_A2hi[MM*HH], g_A2lo[MM*HH];   // attention-out fp16 hi/lo
__device__ __half g_H2[MM*HH];                    // h2 fp16 (vocab A)
__device__ __half g_W0h[HH*EE];
__device__ __half g_W1h[HH*HH];
__device__ __half g_Wqh[3*HH*HH];
__device__ __half g_Woh[HH*HH];
__device__ __half g_Bh[(size_t)VV*HH];            // vocab weights fp16
__device__ __half g_Qh[32*1024*64];               // Q fp16 [bh][s][d]
__device__ __half g_Kh[32*1024*64];               // K fp16 [bh][s][d]
__device__ __half g_Vth[32*128*1024];             // V fp16 transposed [bh][d pad128][k]; pad rows stay 0
__device__ __half g_Sh[(size_t)32*1024*1024];     // P~ fp16

__device__ __forceinline__ uint32_t smem_u32(const void* p) {
    uint32_t a;
    asm("{ .reg .u64 t; cvta.to.shared.u64 t, %1; cvt.u32.u64 %0, t; }" : "=r"(a) : "l"(p));
    return a;
}
__device__ __forceinline__ void cp_async16(uint32_t dst, const void* src) {
    asm volatile("cp.async.cg.shared.global [%0], [%1], 16;" :: "r"(dst), "l"(src));
}
__device__ __forceinline__ void ldsm_x4(uint32_t& r0, uint32_t& r1, uint32_t& r2, uint32_t& r3,
                                        uint32_t addr) {
    asm volatile("ldmatrix.sync.aligned.m8n8.x4.shared.b16 {%0,%1,%2,%3}, [%4];"
                 : "=r"(r0), "=r"(r1), "=r"(r2), "=r"(r3) : "r"(addr));
}
__device__ __forceinline__ void mma_f16(float* c, const uint32_t* a, const uint32_t* b) {
    asm volatile("mma.sync.aligned.m16n8k16.row.col.f32.f16.f16.f32 "
                 "{%0,%1,%2,%3}, {%4,%5,%6,%7}, {%8,%9}, {%0,%1,%2,%3};"
                 : "+f"(c[0]), "+f"(c[1]), "+f"(c[2]), "+f"(c[3])
                 : "r"(a[0]), "r"(a[1]), "r"(a[2]), "r"(a[3]), "r"(b[0]), "r"(b[1]));
}

// ---------------- merged preprocessing ----------------
#define N_VOC ((long long)VV*HH)
#define N_W0  (HH*EE)
#define N_W1  (HH*HH)
#define N_WQ  (3*HH*HH)
#define N_WO  (HH*HH)
#define N_EMB (MM*EE)
#define N_PREP (N_VOC + N_W0 + N_W1 + N_WQ + N_WO + N_EMB)

__global__ void prep_kernel(const float* __restrict__ out_w,
                            const float* __restrict__ W0,
                            const float* __restrict__ W1,
                            const float* __restrict__ Wq,
                            const float* __restrict__ Wo,
                            const int* __restrict__ x,
                            const float* __restrict__ emb) {
    long long idx = (long long)blockIdx.x * blockDim.x + threadIdx.x;
    if (idx < N_VOC) { g_Bh[idx] = __float2half(out_w[idx]); return; }
    idx -= N_VOC;
    if (idx < N_W0) { g_W0h[idx] = __float2half(W0[idx]); return; }
    idx -= N_W0;
    if (idx < N_W1) { g_W1h[idx] = __float2half(W1[idx]); return; }
    idx -= N_W1;
    if (idx < N_WQ) { g_Wqh[idx] = __float2half(Wq[idx]); return; }
    idx -= N_WQ;
    if (idx < N_WO) { g_Woh[idx] = __float2half(Wo[idx]); return; }
    idx -= N_WO;
    if (idx >= N_EMB) return;
    int i = (int)idx;
    int m = i >> 9;
    int e = i & 511;
    int s = m & (SS - 1);
    int tok = x[m];
    int i2 = e & ~1;
    float freq = expf((float)i2 * (-9.210340371976184f / 512.0f));
    float ang = (float)s * freq;
    float pe = (e & 1) ? cosf(ang) : sinf(ang);
    float v = emb[(size_t)tok * EE + e] + pe;
    __half h = __float2half(v);
    g_Ahi[i] = h;
    g_Alo[i] = __float2half(v - __half2float(h));
}

// ============== fp16 NT GEMM, 1- or 2-term A ==============
// output modes: fp32 C_ | fp16 hi/lo split Chi_/Clo_ (optionally scaled by 1/Ldiv row sums)
//               | single fp16 Fh_ | exp-fp16 Fh_ with row-sum atomics into Lsum_
#define SPAD 40
#define TILE_E (128*SPAD)
#define GF_SMEM (2*3*TILE_E*2)    // 61440 bytes

__global__ __launch_bounds__(256, 2) void gemm_f16_mma(
    const __half* __restrict__ Ahi_, const __half* __restrict__ Alo_,
    const __half* __restrict__ B_,
    const float* __restrict__ bias, float* __restrict__ C_,
    __half* __restrict__ Chi_, __half* __restrict__ Clo_,
    __half* __restrict__ Fh_,
    float* __restrict__ Lsum_, const float* __restrict__ Ldiv_,
    long long ls1, long long ls2,
    int K, int lda, int ldb, int ldc, int nValid, float scale,
    int zmod, long long sA1, long long sA2, long long sB1, long long sB2,
    long long sC1, long long sC2)
{
    extern __shared__ __align__(16) __half smh[];
    const uint32_t smb = smem_u32(smh);

    const int tid = threadIdx.x;
    const int lane = tid & 31;
    const int wid = tid >> 5;
    const int warp_m = wid >> 2;
    const int warp_n = wid & 3;
    const int bm = blockIdx.y * 128;
    const int bn = blockIdx.x * 128;
    const bool two = (Alo_ != nullptr);

    const int z = blockIdx.z;
    const int z1 = z % zmod, z2 = z / zmod;
    const long long offA = (long long)z1 * sA1 + (long long)z2 * sA2;
    const long long offB = (long long)z1 * sB1 + (long long)z2 * sB2;
    const long long offC = (long long)z1 * sC1 + (long long)z2 * sC2;
    const long long lbase = (long long)z1 * ls1 + (long long)z2 * ls2;

    const __half* pT[3] = { Ahi_ + offA + (size_t)bm * lda,
                            two ? (Alo_ + offA + (size_t)bm * lda) : nullptr,
                            B_   + offB + (size_t)bn * ldb };

    float acc[4][4][4];
    #pragma unroll
    for (int i = 0; i < 4; i++)
        #pragma unroll
        for (int j = 0; j < 4; j++)
            #pragma unroll
            for (int r = 0; r < 4; r++) acc[i][j][r] = 0.f;

    const int lrow = tid >> 2;
    const int lcol = (tid & 3) * 8;
    const int nstages = K >> 5;

    auto prefetch = [&](int s) {
        const int gk = s * 32;
        const uint32_t base = smb + (uint32_t)((s & 1) * 3 * TILE_E) * 2;
        #pragma unroll
        for (int t = 0; t < 3; t++) {
            if (t == 1 && !two) continue;
            const __half* src = pT[t] + gk + lcol;
            const int ld = (t < 2) ? lda : ldb;
            #pragma unroll
            for (int c = 0; c < 2; c++) {
                int row = lrow + c * 64;
                cp_async16(base + (uint32_t)(t * TILE_E + row * SPAD + lcol) * 2,
                           src + (size_t)row * ld);
            }
        }
    };

    prefetch(0);
    asm volatile("cp.async.commit_group;");

    for (int s = 0; s < nstages; s++) {
        if (s < nstages - 1) {
            prefetch(s + 1);
            asm volatile("cp.async.commit_group;");
            asm volatile("cp.async.wait_group 1;");
        } else {
            asm volatile("cp.async.wait_group 0;");
        }
        __syncthreads();

        const uint32_t stg = smb + (uint32_t)((s & 1) * 3 * TILE_E) * 2;
        const uint32_t tAhi = stg;
        const uint32_t tAlo = stg + TILE_E * 2;
        const uint32_t tB   = stg + 2 * TILE_E * 2;
        const int q  = lane >> 3;
        const int rr = lane & 7;

        #pragma unroll
        for (int ko = 0; ko < 32; ko += 16) {
            const int arow = warp_m * 64 + (q & 1) * 8 + rr;
            const int acol = ko + (q >> 1) * 8;
            const int brow = warp_n * 32 + (q >> 1) * 8 + rr;
            const int bcol = ko + (q & 1) * 8;

            uint32_t b[4][2];
            #pragma unroll
            for (int j = 0; j < 2; j++)
                ldsm_x4(b[2*j][0], b[2*j][1], b[2*j+1][0], b[2*j+1][1],
                        tB + (uint32_t)((brow + j * 16) * SPAD + bcol) * 2);
            uint32_t aH[4][4];
            #pragma unroll
            for (int i = 0; i < 4; i++)
                ldsm_x4(aH[i][0], aH[i][1], aH[i][2], aH[i][3],
                        tAhi + (uint32_t)((arow + i * 16) * SPAD + acol) * 2);
            #pragma unroll
            for (int i = 0; i < 4; i++)
                #pragma unroll
                for (int j = 0; j < 4; j++)
                    mma_f16(acc[i][j], aH[i], b[j]);
            if (two) {
                uint32_t aL[4][4];
                #pragma unroll
                for (int i = 0; i < 4; i++)
                    ldsm_x4(aL[i][0], aL[i][1], aL[i][2], aL[i][3],
                            tAlo + (uint32_t)((arow + i * 16) * SPAD + acol) * 2);
                #pragma unroll
                for (int i = 0; i < 4; i++)
                    #pragma unroll
                    for (int j = 0; j < 4; j++)
                        mma_f16(acc[i][j], aL[i], b[j]);
            }
        }
        __syncthreads();
    }

    const int gr = lane >> 2;
    const int gc = (lane & 3) * 2;

    if (Lsum_) {
        // exp-fp16 mode: Fh = exp(scale*acc), row sums -> atomics
        __half* Fh = Fh_ + offC;
        float rs[4][2];
        #pragma unroll
        for (int i = 0; i < 4; i++) { rs[i][0] = 0.f; rs[i][1] = 0.f; }
        #pragma unroll
        for (int j = 0; j < 4; j++) {
            int col = bn + warp_n * 32 + j * 8 + gc;
            #pragma unroll
            for (int i = 0; i < 4; i++) {
                int row0 = bm + warp_m * 64 + i * 16 + gr;
                float e00 = __expf(fminf(acc[i][j][0]*scale, 10.5f));
                float e01 = __expf(fminf(acc[i][j][1]*scale, 10.5f));
                float e10 = __expf(fminf(acc[i][j][2]*scale, 10.5f));
                float e11 = __expf(fminf(acc[i][j][3]*scale, 10.5f));
                *(__half2*)(Fh + (size_t)row0 * ldc + col)       = __floats2half2_rn(e00, e01);
                *(__half2*)(Fh + (size_t)(row0 + 8) * ldc + col) = __floats2half2_rn(e10, e11);
                rs[i][0] += e00 + e01;
                rs[i][1] += e10 + e11;
            }
        }
        #pragma unroll
        for (int i = 0; i < 4; i++)
            #pragma unroll
            for (int hh = 0; hh < 2; hh++) {
                float v = rs[i][hh];
                v += __shfl_xor_sync(0xffffffffu, v, 1);
                v += __shfl_xor_sync(0xffffffffu, v, 2);
                rs[i][hh] = v;
            }
        if ((lane & 3) == 0) {
            #pragma unroll
            for (int i = 0; i < 4; i++) {
                int row0 = bm + warp_m * 64 + i * 16 + gr;
                atomicAdd(Lsum_ + lbase + row0,     rs[i][0]);
                atomicAdd(Lsum_ + lbase + row0 + 8, rs[i][1]);
            }
        }
        return;
    }

    float* C = C_ ? C_ + offC : nullptr;
    __half* Chi = Chi_ ? Chi_ + offC : nullptr;
    __half* Clo = Clo_ ? Clo_ + offC : nullptr;
    __half* Fh = Fh_ ? Fh_ + offC : nullptr;

    #pragma unroll
    for (int j = 0; j < 4; j++) {
        int col = bn + warp_n * 32 + j * 8 + gc;
        if (col >= nValid) continue;
        float2 bv = make_float2(0.f, 0.f);
        if (bias) bv = *(const float2*)(bias + col);
        #pragma unroll
        for (int i = 0; i < 4; i++) {
            int row0 = bm + warp_m * 64 + i * 16 + gr;
            float s0 = scale, s1 = scale;
            if (Ldiv_) {
                s0 = scale / Ldiv_[lbase + row0];
                s1 = scale / Ldiv_[lbase + row0 + 8];
            }
            float v00 = acc[i][j][0]*s0 + bv.x, v01 = acc[i][j][1]*s0 + bv.y;
            float v10 = acc[i][j][2]*s1 + bv.x, v11 = acc[i][j][3]*s1 + bv.y;
            size_t o0 = (size_t)row0 * ldc + col;
            size_t o1 = (size_t)(row0 + 8) * ldc + col;
            if (Chi) {
                __half h;
                h = __float2half(v00); Chi[o0]   = h; Clo[o0]   = __float2half(v00 - __half2float(h));
                h = __float2half(v01); Chi[o0+1] = h; Clo[o0+1] = __float2half(v01 - __half2float(h));
                h = __float2half(v10); Chi[o1]   = h; Clo[o1]   = __float2half(v10 - __half2float(h));
                h = __float2half(v11); Chi[o1+1] = h; Clo[o1+1] = __float2half(v11 - __half2float(h));
            } else if (Fh) {
                *(__half2*)(Fh + o0) = __floats2half2_rn(v00, v01);
                *(__half2*)(Fh + o1) = __floats2half2_rn(v10, v11);
            } else {
                *(float2*)(C + o0) = make_float2(v00, v01);
                *(float2*)(C + o1) = make_float2(v10, v11);
            }
        }
    }
}

// ---------------- parallel liquid scan (exact affine chunk decomposition) ----------------
__global__ __launch_bounds__(512) void liquid_scan_par(
    const float* __restrict__ I, const float* __restrict__ tau,
    const float* __restrict__ log_dt, float* __restrict__ out) {
    const int b = blockIdx.x;
    const int lg = blockIdx.y;
    const int lane16 = threadIdx.x & 15;
    const int chunk  = threadIdx.x >> 4;
    const int o = lg * 16 + lane16;
    const float dt = expf(log_dt[0]);
    const float r = dt / tau[o];
    const float a = 1.f - r;
    const float* Ib = I + (size_t)b * SS * HH + o;
    const int t0 = chunk * 32;

    float Iv[32];
    #pragma unroll
    for (int i = 0; i < 32; i++) Iv[i] = Ib[(size_t)(t0 + i) * HH];

    float u = 0.f, s = 0.f;
    #pragma unroll
    for (int i = 0; i < 32; i++) {
        float sn = s + r * (u - s);
        u = u + r * (Iv[i] - u);
        s = sn;
    }
    __shared__ float2 dloc[32][16];
    __shared__ float2 st[32][16];
    dloc[chunk][lane16] = make_float2(u, s);
    __syncthreads();

    if (chunk == 0) {
        float a2 = a*a, a4 = a2*a2, a8 = a4*a4, a16 = a8*a8;
        float a32v = a16*a16;
        float a31 = a16*a8*a4*a2*a;
        float c32 = 32.f * r * a31;
        float2 x = make_float2(0.f, 0.f);
        #pragma unroll
        for (int c = 0; c < 32; c++) {
            st[c][lane16] = x;
            float2 d = dloc[c][lane16];
            float nu = a32v * x.x + d.x;
            float ns = c32 * x.x + a32v * x.y + d.y;
            x = make_float2(nu, ns);
        }
    }
    __syncthreads();

    float2 x0 = st[chunk][lane16];
    u = x0.x; s = x0.y;
    float* Ob = out + (size_t)b * SS * HH + o;
    #pragma unroll
    for (int i = 0; i < 32; i++) {
        float sn = s + r * (u - s);
        u = u + r * (Iv[i] - u);
        s = sn;
        Ob[(size_t)(t0 + i) * HH] = tanhf(s);
    }
}

// ---------------- layernorm -> fp16 hi/lo ----------------
__global__ void layernorm_split(const float* __restrict__ in, const float* __restrict__ g,
                                const float* __restrict__ be,
                                __half* __restrict__ hi, __half* __restrict__ lo) {
    int row = blockIdx.x;
    int tid = threadIdx.x;
    const float* p = in + (size_t)row * HH;
    float a = p[tid], b = p[tid + 256];
    float sum = a + b, sq = a*a + b*b;
    __shared__ float s1[8], s2[8];
    #pragma unroll
    for (int o = 16; o; o >>= 1) {
        sum += __shfl_xor_sync(0xffffffffu, sum, o);
        sq  += __shfl_xor_sync(0xffffffffu, sq,  o);
    }
    if ((tid & 31) == 0) { s1[tid>>5] = sum; s2[tid>>5] = sq; }
    __syncthreads();
    sum = 0.f; sq = 0.f;
    #pragma unroll
    for (int i = 0; i < 8; i++) { sum += s1[i]; sq += s2[i]; }
    float mean = sum * (1.f/512.f);
    float var  = sq * (1.f/512.f) - mean*mean;
    float inv = rsqrtf(var + 1e-5f);
    float y0 = (a - mean) * inv * g[tid]       + be[tid];
    float y1 = (b - mean) * inv * g[tid + 256] + be[tid + 256];
    size_t base = (size_t)row * HH;
    __half h0 = __float2half(y0);
    __half h1 = __float2half(y1);
    hi[base + tid]       = h0;
    hi[base + tid + 256] = h1;
    lo[base + tid]       = __float2half(y0 - __half2float(h0));
    lo[base + tid + 256] = __float2half(y1 - __half2float(h1));
}

// ---------------- qkv split: Q/K fp16 [bh][s][d], V fp16 transposed; also zero g_l ----------------
__global__ void qkv_split_kernel(const float* __restrict__ qkv) {
    int idx = blockIdx.x * blockDim.x + threadIdx.x;
    if (idx < 32*1024) g_l[idx] = 0.f;
    if (idx >= MM * 1536) return;
    int row = idx / 1536;
    int col = idx - row * 1536;
    int b = row >> 10, s = row & 1023;
    float v = qkv[idx];
    if (col < 512) {
        int hd = col >> 6, d = col & 63;
        g_Qh[((size_t)(b*8 + hd) * 1024 + s) * 64 + d] = __float2half(v);
    } else if (col < 1024) {
        int c = col - 512;
        int hd = c >> 6, d = c & 63;
        g_Kh[((size_t)(b*8 + hd) * 1024 + s) * 64 + d] = __float2half(v);
    } else {
        int c = col - 1024;
        int hd = c >> 6, d = c & 63;
        g_Vth[(size_t)(b*8 + hd) * 131072 + (size_t)d * 1024 + s] = __float2half(v);
    }
}

// ---------------- host orchestration ----------------
extern "C" void kernel_launch(void* const* d_in, const int* in_sizes, int n_in,
                              void* d_out, int out_size) {
    const int*   x          = (const int*)  d_in[0];
    const float* emb        = (const float*)d_in[1];
    const float* W0         = (const float*)d_in[2];
    const float* b0         = (const float*)d_in[3];
    const float* tau0       = (const float*)d_in[4];
    const float* g0         = (const float*)d_in[5];
    const float* be0        = (const float*)d_in[6];
    const float* W1         = (const float*)d_in[7];
    const float* b1         = (const float*)d_in[8];
    const float* tau1       = (const float*)d_in[9];
    const float* g1         = (const float*)d_in[10];
    const float* be1        = (const float*)d_in[11];
    const float* attn_in_w  = (const float*)d_in[12];
    const float* attn_in_b  = (const float*)d_in[13];
    const float* attn_out_w = (const float*)d_in[14];
    const float* attn_out_b = (const float*)d_in[15];
    const float* out_w      = (const float*)d_in[16];
    const float* out_b      = (const float*)d_in[17];
    const float* log_dt     = (const float*)d_in[18];
    float* out = (float*)d_out;

    float *I, *sbuf, *qkv, *lsum;
    __half *Ahi, *Alo, *A2hi, *A2lo, *H2;
    __half *W0h, *W1h, *Wqh, *Woh, *Bh, *Qh, *Kh, *Vth, *Sh;
    cudaGetSymbolAddress((void**)&I,      g_I);
    cudaGetSymbolAddress((void**)&sbuf,   g_s);
    cudaGetSymbolAddress((void**)&qkv,    g_qkv);
    cudaGetSymbolAddress((void**)&lsum,   g_l);
    cudaGetSymbolAddress((void**)&Ahi,    g_Ahi);
    cudaGetSymbolAddress((void**)&Alo,    g_Alo);
    cudaGetSymbolAddress((void**)&A2hi,   g_A2hi);
    cudaGetSymbolAddress((void**)&A2lo,   g_A2lo);
    cudaGetSymbolAddress((void**)&H2,     g_H2);
    cudaGetSymbolAddress((void**)&Bh,     g_Bh);
    cudaGetSymbolAddress((void**)&W0h,    g_W0h);
    cudaGetSymbolAddress((void**)&W1h,    g_W1h);
    cudaGetSymbolAddress((void**)&Wqh,    g_Wqh);
    cudaGetSymbolAddress((void**)&Woh,    g_Woh);
    cudaGetSymbolAddress((void**)&Qh,     g_Qh);
    cudaGetSymbolAddress((void**)&Kh,     g_Kh);
    cudaGetSymbolAddress((void**)&Vth,    g_Vth);
    cudaGetSymbolAddress((void**)&Sh,     g_Sh);

    cudaFuncSetAttribute(gemm_f16_mma,
                         cudaFuncAttributeMaxDynamicSharedMemorySize, GF_SMEM);

    // merged preprocessing
    prep_kernel<<<(unsigned)((N_PREP + 255)/256), 256>>>(out_w, W0, W1, attn_in_w, attn_out_w, x, emb);

    // 2. liquid layer 0 (fp16: exact A hi/lo x rounded W)
    gemm_f16_mma<<<dim3(4, 32, 1), 256, GF_SMEM>>>(
        Ahi, Alo, W0h, b0, I, nullptr, nullptr, nullptr, nullptr, nullptr, 0, 0,
        EE, EE, EE, HH, HH, 1.f, 1, 0,0,0,0,0,0);
    liquid_scan_par<<<dim3(BB, 32), 512>>>(I, tau0, log_dt, sbuf);
    layernorm_split<<<MM, 256>>>(sbuf, g0, be0, Ahi, Alo);

    // 3. liquid layer 1
    gemm_f16_mma<<<dim3(4, 32, 1), 256, GF_SMEM>>>(
        Ahi, Alo, W1h, b1, I, nullptr, nullptr, nullptr, nullptr, nullptr, 0, 0,
        HH, HH, HH, HH, HH, 1.f, 1, 0,0,0,0,0,0);
    liquid_scan_par<<<dim3(BB, 32), 512>>>(I, tau1, log_dt, sbuf);
    layernorm_split<<<MM, 256>>>(sbuf, g1, be1, Ahi, Alo);

    // 4. MHA: qkv projection (fp16 2-term A)
    gemm_f16_mma<<<dim3(12, 32, 1), 256, GF_SMEM>>>(
        Ahi, Alo, Wqh, attn_in_b, qkv, nullptr, nullptr, nullptr, nullptr, nullptr, 0, 0,
        HH, HH, HH, 3*HH, 3*HH, 1.f, 1, 0,0,0,0,0,0);
    qkv_split_kernel<<<(MM*1536 + 255)/256, 256>>>(qkv);

    // scores + fused exp + row-sum atomics: P~ = exp(QK^T/8) -> Sh, sums -> g_l
    gemm_f16_mma<<<dim3(8, 8, 32), 256, GF_SMEM>>>(
        Qh, nullptr, Kh, nullptr, nullptr, nullptr, nullptr, Sh, lsum, nullptr, 1024, 0,
        64, 64, 64, 1024, 1024, 0.125f,
        32, 65536LL, 0, 65536LL, 0, 1LL<<20, 0);

    // AV = P~ @ Vt^T with fused 1/l normalization -> fp16 hi/lo A2
    gemm_f16_mma<<<dim3(1, 8, 32), 256, GF_SMEM>>>(
        Sh, nullptr, Vth, nullptr, nullptr, A2hi, A2lo, nullptr, nullptr, lsum, 1024, 8192,
        1024, 1024, 1024, 512, 64, 1.f,
        8, 1LL<<20, 8LL<<20, 131072LL, 8LL*131072, 64LL, 524288LL);

    // out-projection (fp16 2-term A) -> single fp16 H2
    gemm_f16_mma<<<dim3(4, 32, 1), 256, GF_SMEM>>>(
        A2hi, A2lo, Woh, attn_out_b, nullptr, nullptr, nullptr, H2, nullptr, nullptr, 0, 0,
        HH, HH, HH, HH, HH, 1.f, 1, 0,0,0,0,0,0);

    // 5. vocab projection (fp16 1-term)
    gemm_f16_mma<<<dim3(VV/128, MM/128, 1), 256, GF_SMEM>>>(
        H2, nullptr, Bh, out_b, out, nullptr, nullptr, nullptr, nullptr, nullptr, 0, 0,
        HH, HH, HH, VV, VV, 1.f, 1, 0,0,0,0,0,0);
}

// round 16
// speedup vs baseline: 1.4758x; 1.0276x over previous
#include <cuda_runtime.h>
#include <cuda_bf16.h>
#include <cuda_fp16.h>
#include <cstdint>
#include <math.h>

#define BB 4
#define SS 1024
#define EE 512
#define HH 512
#define VV 32000
#define MM (BB*SS)      // 4096
#define NH 8
#define DH 64

// ---------------- scratch (static device memory; no allocations) ----------------
__device__ float g_I[MM*HH];
__device__ float g_s[MM*HH];
__device__ float g_l[32*1024];                    // attention row sums (atomic)
__device__ __half g_Ahi[MM*HH],  g_Alo[MM*HH];    // activation fp16 hi/lo
__device__ __half g_A2hi[MM*HH], g_A2lo[MM*HH];   // attention-out fp16 hi/lo
__device__ __half g_H2[MM*HH];                    // h2 fp16 (vocab A)
__device__ __half g_W0h[HH*EE];
__device__ __half g_W1h[HH*HH];
__device__ __half g_Wqh[3*HH*HH];
__device__ __half g_Woh[HH*HH];
__device__ __half g_Bh[(size_t)VV*HH];            // vocab weights fp16
__device__ __half g_Qh[32*1024*64];               // Q fp16 [bh][s][d]
__device__ __half g_Kh[32*1024*64];               // K fp16 [bh][s][d]
__device__ __half g_Vth[32*128*1024];             // V fp16 transposed [bh][d pad128][k]; pad rows stay 0
__device__ __half g_Sh[(size_t)32*1024*1024];     // P~ fp16

__device__ __forceinline__ uint32_t smem_u32(const void* p) {
    uint32_t a;
    asm("{ .reg .u64 t; cvta.to.shared.u64 t, %1; cvt.u32.u64 %0, t; }" : "=r"(a) : "l"(p));
    return a;
}
__device__ __forceinline__ void cp_async16(uint32_t dst, const void* src) {
    asm volatile("cp.async.cg.shared.global [%0], [%1], 16;" :: "r"(dst), "l"(src));
}
__device__ __forceinline__ void ldsm_x4(uint32_t& r0, uint32_t& r1, uint32_t& r2, uint32_t& r3,
                                        uint32_t addr) {
    asm volatile("ldmatrix.sync.aligned.m8n8.x4.shared.b16 {%0,%1,%2,%3}, [%4];"
                 : "=r"(r0), "=r"(r1), "=r"(r2), "=r"(r3) : "r"(addr));
}
__device__ __forceinline__ void mma_f16(float* c, const uint32_t* a, const uint32_t* b) {
    asm volatile("mma.sync.aligned.m16n8k16.row.col.f32.f16.f16.f32 "
                 "{%0,%1,%2,%3}, {%4,%5,%6,%7}, {%8,%9}, {%0,%1,%2,%3};"
                 : "+f"(c[0]), "+f"(c[1]), "+f"(c[2]), "+f"(c[3])
                 : "r"(a[0]), "r"(a[1]), "r"(a[2]), "r"(a[3]), "r"(b[0]), "r"(b[1]));
}

// ---------------- merged preprocessing ----------------
#define N_VOC ((long long)VV*HH)
#define N_W0  (HH*EE)
#define N_W1  (HH*HH)
#define N_WQ  (3*HH*HH)
#define N_WO  (HH*HH)
#define N_EMB (MM*EE)
#define N_PREP (N_VOC + N_W0 + N_W1 + N_WQ + N_WO + N_EMB)

__global__ void prep_kernel(const float* __restrict__ out_w,
                            const float* __restrict__ W0,
                            const float* __restrict__ W1,
                            const float* __restrict__ Wq,
                            const float* __restrict__ Wo,
                            const int* __restrict__ x,
                            const float* __restrict__ emb) {
    long long idx = (long long)blockIdx.x * blockDim.x + threadIdx.x;
    if (idx < 32*1024) g_l[idx] = 0.f;     // zero attention row sums every run
    if (idx < N_VOC) { g_Bh[idx] = __float2half(out_w[idx]); return; }
    idx -= N_VOC;
    if (idx < N_W0) { g_W0h[idx] = __float2half(W0[idx]); return; }
    idx -= N_W0;
    if (idx < N_W1) { g_W1h[idx] = __float2half(W1[idx]); return; }
    idx -= N_W1;
    if (idx < N_WQ) { g_Wqh[idx] = __float2half(Wq[idx]); return; }
    idx -= N_WQ;
    if (idx < N_WO) { g_Woh[idx] = __float2half(Wo[idx]); return; }
    idx -= N_WO;
    if (idx >= N_EMB) return;
    int i = (int)idx;
    int m = i >> 9;
    int e = i & 511;
    int s = m & (SS - 1);
    int tok = x[m];
    int i2 = e & ~1;
    float freq = expf((float)i2 * (-9.210340371976184f / 512.0f));
    float ang = (float)s * freq;
    float pe = (e & 1) ? cosf(ang) : sinf(ang);
    float v = emb[(size_t)tok * EE + e] + pe;
    __half h = __float2half(v);
    g_Ahi[i] = h;
    g_Alo[i] = __float2half(v - __half2float(h));
}

// ============== fp16 NT GEMM, 1- or 2-term A ==============
// output modes (priority order):
//   qkvmode: scatter into Q/K/V attention layouts (Chi_=Q, Clo_=K, Fh_=Vt)
//   Lsum_:   exp-fp16 into Fh_ with row-sum atomics
//   Chi_:    fp16 hi/lo split (optionally scaled by 1/Ldiv row sums)
//   Fh_:     single fp16
//   else:    fp32 C_
#define SPAD 40
#define TILE_E (128*SPAD)
#define GF_SMEM (2*3*TILE_E*2)    // 61440 bytes

__global__ __launch_bounds__(256, 2) void gemm_f16_mma(
    const __half* __restrict__ Ahi_, const __half* __restrict__ Alo_,
    const __half* __restrict__ B_,
    const float* __restrict__ bias, float* __restrict__ C_,
    __half* __restrict__ Chi_, __half* __restrict__ Clo_,
    __half* __restrict__ Fh_,
    float* __restrict__ Lsum_, const float* __restrict__ Ldiv_,
    long long ls1, long long ls2, int qkvmode,
    int K, int lda, int ldb, int ldc, int nValid, float scale,
    int zmod, long long sA1, long long sA2, long long sB1, long long sB2,
    long long sC1, long long sC2)
{
    extern __shared__ __align__(16) __half smh[];
    const uint32_t smb = smem_u32(smh);

    const int tid = threadIdx.x;
    const int lane = tid & 31;
    const int wid = tid >> 5;
    const int warp_m = wid >> 2;
    const int warp_n = wid & 3;
    const int bm = blockIdx.y * 128;
    const int bn = blockIdx.x * 128;
    const bool two = (Alo_ != nullptr);

    const int z = blockIdx.z;
    const int z1 = z % zmod, z2 = z / zmod;
    const long long offA = (long long)z1 * sA1 + (long long)z2 * sA2;
    const long long offB = (long long)z1 * sB1 + (long long)z2 * sB2;
    const long long offC = (long long)z1 * sC1 + (long long)z2 * sC2;
    const long long lbase = (long long)z1 * ls1 + (long long)z2 * ls2;

    const __half* pT[3] = { Ahi_ + offA + (size_t)bm * lda,
                            two ? (Alo_ + offA + (size_t)bm * lda) : nullptr,
                            B_   + offB + (size_t)bn * ldb };

    float acc[4][4][4];
    #pragma unroll
    for (int i = 0; i < 4; i++)
        #pragma unroll
        for (int j = 0; j < 4; j++)
            #pragma unroll
            for (int r = 0; r < 4; r++) acc[i][j][r] = 0.f;

    const int lrow = tid >> 2;
    const int lcol = (tid & 3) * 8;
    const int nstages = K >> 5;

    auto prefetch = [&](int s) {
        const int gk = s * 32;
        const uint32_t base = smb + (uint32_t)((s & 1) * 3 * TILE_E) * 2;
        #pragma unroll
        for (int t = 0; t < 3; t++) {
            if (t == 1 && !two) continue;
            const __half* src = pT[t] + gk + lcol;
            const int ld = (t < 2) ? lda : ldb;
            #pragma unroll
            for (int c = 0; c < 2; c++) {
                int row = lrow + c * 64;
                cp_async16(base + (uint32_t)(t * TILE_E + row * SPAD + lcol) * 2,
                           src + (size_t)row * ld);
            }
        }
    };

    prefetch(0);
    asm volatile("cp.async.commit_group;");

    for (int s = 0; s < nstages; s++) {
        if (s < nstages - 1) {
            prefetch(s + 1);
            asm volatile("cp.async.commit_group;");
            asm volatile("cp.async.wait_group 1;");
        } else {
            asm volatile("cp.async.wait_group 0;");
        }
        __syncthreads();

        const uint32_t stg = smb + (uint32_t)((s & 1) * 3 * TILE_E) * 2;
        const uint32_t tAhi = stg;
        const uint32_t tAlo = stg + TILE_E * 2;
        const uint32_t tB   = stg + 2 * TILE_E * 2;
        const int q  = lane >> 3;
        const int rr = lane & 7;

        #pragma unroll
        for (int ko = 0; ko < 32; ko += 16) {
            const int arow = warp_m * 64 + (q & 1) * 8 + rr;
            const int acol = ko + (q >> 1) * 8;
            const int brow = warp_n * 32 + (q >> 1) * 8 + rr;
            const int bcol = ko + (q & 1) * 8;

            uint32_t b[4][2];
            #pragma unroll
            for (int j = 0; j < 2; j++)
                ldsm_x4(b[2*j][0], b[2*j][1], b[2*j+1][0], b[2*j+1][1],
                        tB + (uint32_t)((brow + j * 16) * SPAD + bcol) * 2);
            uint32_t aH[4][4];
            #pragma unroll
            for (int i = 0; i < 4; i++)
                ldsm_x4(aH[i][0], aH[i][1], aH[i][2], aH[i][3],
                        tAhi + (uint32_t)((arow + i * 16) * SPAD + acol) * 2);
            #pragma unroll
            for (int i = 0; i < 4; i++)
                #pragma unroll
                for (int j = 0; j < 4; j++)
                    mma_f16(acc[i][j], aH[i], b[j]);
            if (two) {
                uint32_t aL[4][4];
                #pragma unroll
                for (int i = 0; i < 4; i++)
                    ldsm_x4(aL[i][0], aL[i][1], aL[i][2], aL[i][3],
                            tAlo + (uint32_t)((arow + i * 16) * SPAD + acol) * 2);
                #pragma unroll
                for (int i = 0; i < 4; i++)
                    #pragma unroll
                    for (int j = 0; j < 4; j++)
                        mma_f16(acc[i][j], aL[i], b[j]);
            }
        }
        __syncthreads();
    }

    const int gr = lane >> 2;
    const int gc = (lane & 3) * 2;

    if (qkvmode) {
        // scatter into attention layouts; block's bn region is uniform (128 | 512)
        __half* Qd = Chi_;
        __half* Kd = Clo_;
        __half* Vd = Fh_;
        #pragma unroll
        for (int j = 0; j < 4; j++) {
            int col = bn + warp_n * 32 + j * 8 + gc;
            float2 bv = *(const float2*)(bias + col);
            #pragma unroll
            for (int i = 0; i < 4; i++) {
                int row0 = bm + warp_m * 64 + i * 16 + gr;
                float v00 = acc[i][j][0] + bv.x, v01 = acc[i][j][1] + bv.y;
                float v10 = acc[i][j][2] + bv.x, v11 = acc[i][j][3] + bv.y;
                int b0 = row0 >> 10, s0 = row0 & 1023;
                if (col < 1024) {
                    __half* D = (col < 512) ? Qd : Kd;
                    int c = (col < 512) ? col : col - 512;
                    int hd = c >> 6, d = c & 63;
                    size_t o0 = ((size_t)((b0*8 + hd) * 1024 + s0)) * 64 + d;
                    *(__half2*)(D + o0)           = __floats2half2_rn(v00, v01);
                    *(__half2*)(D + o0 + 8*64)    = __floats2half2_rn(v10, v11);
                } else {
                    int c = col - 1024;
                    int hd = c >> 6, d = c & 63;
                    size_t base = (size_t)(b0*8 + hd) * 131072;
                    Vd[base + (size_t)d*1024     + s0]     = __float2half(v00);
                    Vd[base + (size_t)(d+1)*1024 + s0]     = __float2half(v01);
                    Vd[base + (size_t)d*1024     + s0 + 8] = __float2half(v10);
                    Vd[base + (size_t)(d+1)*1024 + s0 + 8] = __float2half(v11);
                }
            }
        }
        return;
    }

    if (Lsum_) {
        // exp-fp16 mode: Fh = exp(scale*acc), row sums -> atomics
        __half* Fh = Fh_ + offC;
        float rs[4][2];
        #pragma unroll
        for (int i = 0; i < 4; i++) { rs[i][0] = 0.f; rs[i][1] = 0.f; }
        #pragma unroll
        for (int j = 0; j < 4; j++) {
            int col = bn + warp_n * 32 + j * 8 + gc;
            #pragma unroll
            for (int i = 0; i < 4; i++) {
                int row0 = bm + warp_m * 64 + i * 16 + gr;
                float e00 = __expf(fminf(acc[i][j][0]*scale, 10.5f));
                float e01 = __expf(fminf(acc[i][j][1]*scale, 10.5f));
                float e10 = __expf(fminf(acc[i][j][2]*scale, 10.5f));
                float e11 = __expf(fminf(acc[i][j][3]*scale, 10.5f));
                *(__half2*)(Fh + (size_t)row0 * ldc + col)       = __floats2half2_rn(e00, e01);
                *(__half2*)(Fh + (size_t)(row0 + 8) * ldc + col) = __floats2half2_rn(e10, e11);
                rs[i][0] += e00 + e01;
                rs[i][1] += e10 + e11;
            }
        }
        #pragma unroll
        for (int i = 0; i < 4; i++)
            #pragma unroll
            for (int hh = 0; hh < 2; hh++) {
                float v = rs[i][hh];
                v += __shfl_xor_sync(0xffffffffu, v, 1);
                v += __shfl_xor_sync(0xffffffffu, v, 2);
                rs[i][hh] = v;
            }
        if ((lane & 3) == 0) {
            #pragma unroll
            for (int i = 0; i < 4; i++) {
                int row0 = bm + warp_m * 64 + i * 16 + gr;
                atomicAdd(Lsum_ + lbase + row0,     rs[i][0]);
                atomicAdd(Lsum_ + lbase + row0 + 8, rs[i][1]);
            }
        }
        return;
    }

    float* C = C_ ? C_ + offC : nullptr;
    __half* Chi = Chi_ ? Chi_ + offC : nullptr;
    __half* Clo = Clo_ ? Clo_ + offC : nullptr;
    __half* Fh = Fh_ ? Fh_ + offC : nullptr;

    #pragma unroll
    for (int j = 0; j < 4; j++) {
        int col = bn + warp_n * 32 + j * 8 + gc;
        if (col >= nValid) continue;
        float2 bv = make_float2(0.f, 0.f);
        if (bias) bv = *(const float2*)(bias + col);
        #pragma unroll
        for (int i = 0; i < 4; i++) {
            int row0 = bm + warp_m * 64 + i * 16 + gr;
            float s0 = scale, s1 = scale;
            if (Ldiv_) {
                s0 = scale / Ldiv_[lbase + row0];
                s1 = scale / Ldiv_[lbase + row0 + 8];
            }
            float v00 = acc[i][j][0]*s0 + bv.x, v01 = acc[i][j][1]*s0 + bv.y;
            float v10 = acc[i][j][2]*s1 + bv.x, v11 = acc[i][j][3]*s1 + bv.y;
            size_t o0 = (size_t)row0 * ldc + col;
            size_t o1 = (size_t)(row0 + 8) * ldc + col;
            if (Chi) {
                __half h;
                h = __float2half(v00); Chi[o0]   = h; Clo[o0]   = __float2half(v00 - __half2float(h));
                h = __float2half(v01); Chi[o0+1] = h; Clo[o0+1] = __float2half(v01 - __half2float(h));
                h = __float2half(v10); Chi[o1]   = h; Clo[o1]   = __float2half(v10 - __half2float(h));
                h = __float2half(v11); Chi[o1+1] = h; Clo[o1+1] = __float2half(v11 - __half2float(h));
            } else if (Fh) {
                *(__half2*)(Fh + o0) = __floats2half2_rn(v00, v01);
                *(__half2*)(Fh + o1) = __floats2half2_rn(v10, v11);
            } else {
                *(float2*)(C + o0) = make_float2(v00, v01);
                *(float2*)(C + o1) = make_float2(v10, v11);
            }
        }
    }
}

// ---------------- parallel liquid scan (exact affine chunk decomposition) ----------------
__global__ __launch_bounds__(512) void liquid_scan_par(
    const float* __restrict__ I, const float* __restrict__ tau,
    const float* __restrict__ log_dt, float* __restrict__ out) {
    const int b = blockIdx.x;
    const int lg = blockIdx.y;
    const int lane16 = threadIdx.x & 15;
    const int chunk  = threadIdx.x >> 4;
    const int o = lg * 16 + lane16;
    const float dt = expf(log_dt[0]);
    const float r = dt / tau[o];
    const float a = 1.f - r;
    const float* Ib = I + (size_t)b * SS * HH + o;
    const int t0 = chunk * 32;

    float Iv[32];
    #pragma unroll
    for (int i = 0; i < 32; i++) Iv[i] = Ib[(size_t)(t0 + i) * HH];

    float u = 0.f, s = 0.f;
    #pragma unroll
    for (int i = 0; i < 32; i++) {
        float sn = s + r * (u - s);
        u = u + r * (Iv[i] - u);
        s = sn;
    }
    __shared__ float2 dloc[32][16];
    __shared__ float2 st[32][16];
    dloc[chunk][lane16] = make_float2(u, s);
    __syncthreads();

    if (chunk == 0) {
        float a2 = a*a, a4 = a2*a2, a8 = a4*a4, a16 = a8*a8;
        float a32v = a16*a16;
        float a31 = a16*a8*a4*a2*a;
        float c32 = 32.f * r * a31;
        float2 x = make_float2(0.f, 0.f);
        #pragma unroll
        for (int c = 0; c < 32; c++) {
            st[c][lane16] = x;
            float2 d = dloc[c][lane16];
            float nu = a32v * x.x + d.x;
            float ns = c32 * x.x + a32v * x.y + d.y;
            x = make_float2(nu, ns);
        }
    }
    __syncthreads();

    float2 x0 = st[chunk][lane16];
    u = x0.x; s = x0.y;
    float* Ob = out + (size_t)b * SS * HH + o;
    #pragma unroll
    for (int i = 0; i < 32; i++) {
        float sn = s + r * (u - s);
        u = u + r * (Iv[i] - u);
        s = sn;
        Ob[(size_t)(t0 + i) * HH] = tanhf(s);
    }
}

// ---------------- layernorm -> fp16 hi/lo ----------------
__global__ void layernorm_split(const float* __restrict__ in, const float* __restrict__ g,
                                const float* __restrict__ be,
                                __half* __restrict__ hi, __half* __restrict__ lo) {
    int row = blockIdx.x;
    int tid = threadIdx.x;
    const float* p = in + (size_t)row * HH;
    float a = p[tid], b = p[tid + 256];
    float sum = a + b, sq = a*a + b*b;
    __shared__ float s1[8], s2[8];
    #pragma unroll
    for (int o = 16; o; o >>= 1) {
        sum += __shfl_xor_sync(0xffffffffu, sum, o);
        sq  += __shfl_xor_sync(0xffffffffu, sq,  o);
    }
    if ((tid & 31) == 0) { s1[tid>>5] = sum; s2[tid>>5] = sq; }
    __syncthreads();
    sum = 0.f; sq = 0.f;
    #pragma unroll
    for (int i = 0; i < 8; i++) { sum += s1[i]; sq += s2[i]; }
    float mean = sum * (1.f/512.f);
    float var  = sq * (1.f/512.f) - mean*mean;
    float inv = rsqrtf(var + 1e-5f);
    float y0 = (a - mean) * inv * g[tid]       + be[tid];
    float y1 = (b - mean) * inv * g[tid + 256] + be[tid + 256];
    size_t base = (size_t)row * HH;
    __half h0 = __float2half(y0);
    __half h1 = __float2half(y1);
    hi[base + tid]       = h0;
    hi[base + tid + 256] = h1;
    lo[base + tid]       = __float2half(y0 - __half2float(h0));
    lo[base + tid + 256] = __float2half(y1 - __half2float(h1));
}

// ---------------- host orchestration ----------------
extern "C" void kernel_launch(void* const* d_in, const int* in_sizes, int n_in,
                              void* d_out, int out_size) {
    const int*   x          = (const int*)  d_in[0];
    const float* emb        = (const float*)d_in[1];
    const float* W0         = (const float*)d_in[2];
    const float* b0         = (const float*)d_in[3];
    const float* tau0       = (const float*)d_in[4];
    const float* g0         = (const float*)d_in[5];
    const float* be0        = (const float*)d_in[6];
    const float* W1         = (const float*)d_in[7];
    const float* b1         = (const float*)d_in[8];
    const float* tau1       = (const float*)d_in[9];
    const float* g1         = (const float*)d_in[10];
    const float* be1        = (const float*)d_in[11];
    const float* attn_in_w  = (const float*)d_in[12];
    const float* attn_in_b  = (const float*)d_in[13];
    const float* attn_out_w = (const float*)d_in[14];
    const float* attn_out_b = (const float*)d_in[15];
    const float* out_w      = (const float*)d_in[16];
    const float* out_b      = (const float*)d_in[17];
    const float* log_dt     = (const float*)d_in[18];
    float* out = (float*)d_out;

    float *I, *sbuf, *lsum;
    __half *Ahi, *Alo, *A2hi, *A2lo, *H2;
    __half *W0h, *W1h, *Wqh, *Woh, *Bh, *Qh, *Kh, *Vth, *Sh;
    cudaGetSymbolAddress((void**)&I,      g_I);
    cudaGetSymbolAddress((void**)&sbuf,   g_s);
    cudaGetSymbolAddress((void**)&lsum,   g_l);
    cudaGetSymbolAddress((void**)&Ahi,    g_Ahi);
    cudaGetSymbolAddress((void**)&Alo,    g_Alo);
    cudaGetSymbolAddress((void**)&A2hi,   g_A2hi);
    cudaGetSymbolAddress((void**)&A2lo,   g_A2lo);
    cudaGetSymbolAddress((void**)&H2,     g_H2);
    cudaGetSymbolAddress((void**)&Bh,     g_Bh);
    cudaGetSymbolAddress((void**)&W0h,    g_W0h);
    cudaGetSymbolAddress((void**)&W1h,    g_W1h);
    cudaGetSymbolAddress((void**)&Wqh,    g_Wqh);
    cudaGetSymbolAddress((void**)&Woh,    g_Woh);
    cudaGetSymbolAddress((void**)&Qh,     g_Qh);
    cudaGetSymbolAddress((void**)&Kh,     g_Kh);
    cudaGetSymbolAddress((void**)&Vth,    g_Vth);
    cudaGetSymbolAddress((void**)&Sh,     g_Sh);

    cudaFuncSetAttribute(gemm_f16_mma,
                         cudaFuncAttributeMaxDynamicSharedMemorySize, GF_SMEM);

    // merged preprocessing (also zeroes g_l)
    prep_kernel<<<(unsigned)((N_PREP + 255)/256), 256>>>(out_w, W0, W1, attn_in_w, attn_out_w, x, emb);

    // 2. liquid layer 0 (fp16: exact A hi/lo x rounded W)
    gemm_f16_mma<<<dim3(4, 32, 1), 256, GF_SMEM>>>(
        Ahi, Alo, W0h, b0, I, nullptr, nullptr, nullptr, nullptr, nullptr, 0, 0, 0,
        EE, EE, EE, HH, HH, 1.f, 1, 0,0,0,0,0,0);
    liquid_scan_par<<<dim3(BB, 32), 512>>>(I, tau0, log_dt, sbuf);
    layernorm_split<<<MM, 256>>>(sbuf, g0, be0, Ahi, Alo);

    // 3. liquid layer 1
    gemm_f16_mma<<<dim3(4, 32, 1), 256, GF_SMEM>>>(
        Ahi, Alo, W1h, b1, I, nullptr, nullptr, nullptr, nullptr, nullptr, 0, 0, 0,
        HH, HH, HH, HH, HH, 1.f, 1, 0,0,0,0,0,0);
    liquid_scan_par<<<dim3(BB, 32), 512>>>(I, tau1, log_dt, sbuf);
    layernorm_split<<<MM, 256>>>(sbuf, g1, be1, Ahi, Alo);

    // 4. MHA: qkv projection with fused Q/K/V scatter epilogue
    gemm_f16_mma<<<dim3(12, 32, 1), 256, GF_SMEM>>>(
        Ahi, Alo, Wqh, attn_in_b, nullptr, Qh, Kh, Vth, nullptr, nullptr, 0, 0, 1,
        HH, HH, HH, 3*HH, 3*HH, 1.f, 1, 0,0,0,0,0,0);

    // scores + fused exp + row-sum atomics: P~ = exp(QK^T/8) -> Sh, sums -> g_l
    gemm_f16_mma<<<dim3(8, 8, 32), 256, GF_SMEM>>>(
        Qh, nullptr, Kh, nullptr, nullptr, nullptr, nullptr, Sh, lsum, nullptr, 1024, 0, 0,
        64, 64, 64, 1024, 1024, 0.125f,
        32, 65536LL, 0, 65536LL, 0, 1LL<<20, 0);

    // AV = P~ @ Vt^T with fused 1/l normalization -> fp16 hi/lo A2
    gemm_f16_mma<<<dim3(1, 8, 32), 256, GF_SMEM>>>(
        Sh, nullptr, Vth, nullptr, nullptr, A2hi, A2lo, nullptr, nullptr, lsum, 1024, 8192, 0,
        1024, 1024, 1024, 512, 64, 1.f,
        8, 1LL<<20, 8LL<<20, 131072LL, 8LL*131072, 64LL, 524288LL);

    // out-projection (fp16 2-term A) -> single fp16 H2
    gemm_f16_mma<<<dim3(4, 32, 1), 256, GF_SMEM>>>(
        A2hi, A2lo, Woh, attn_out_b, nullptr, nullptr, nullptr, H2, nullptr, nullptr, 0, 0, 0,
        HH, HH, HH, HH, HH, 1.f, 1, 0,0,0,0,0,0);

    // 5. vocab projection (fp16 1-term)
    gemm_f16_mma<<<dim3(VV/128, MM/128, 1), 256, GF_SMEM>>>(
        H2, nullptr, Bh, out_b, out, nullptr, nullptr, nullptr, nullptr, nullptr, 0, 0, 0,
        HH, HH, HH, VV, VV, 1.f, 1, 0,0,0,0,0,0);
}

// round 17
// speedup vs baseline: 1.5689x; 1.0631x over previous
#include <cuda_runtime.h>
#include <cuda_bf16.h>
#include <cuda_fp16.h>
#include <cstdint>
#include <math.h>

#define BB 4
#define SS 1024
#define EE 512
#define HH 512
#define VV 32000
#define MM (BB*SS)      // 4096
#define NH 8
#define DH 64

// ---------------- scratch (static device memory; no allocations) ----------------
__device__ float g_I[MM*HH];
__device__ float g_s[MM*HH];
__device__ float g_l[32*1024];                    // attention row sums (atomic)
__device__ __half g_Ahi[MM*HH],  g_Alo[MM*HH];    // activation fp16 hi/lo
__device__ __half g_A2hi[MM*HH], g_A2lo[MM*HH];   // attention-out fp16 hi/lo
__device__ __half g_H2[MM*HH];                    // h2 fp16 (vocab A)
__device__ __half g_W0h[HH*EE];
__device__ __half g_W1h[HH*HH];
__device__ __half g_Wqh[3*HH*HH];
__device__ __half g_Woh[HH*HH];
__device__ __half g_Bh[(size_t)VV*HH];            // vocab weights fp16
__device__ __half g_Qh[32*1024*64];               // Q fp16 [bh][s][d]
__device__ __half g_Kh[32*1024*64];               // K fp16 [bh][s][d]
__device__ __half g_Vth[32*128*1024];             // V fp16 transposed [bh][d pad128][k]; pad rows stay 0
__device__ __half g_Sh[(size_t)32*1024*1024];     // P~ fp16

__device__ __forceinline__ uint32_t smem_u32(const void* p) {
    uint32_t a;
    asm("{ .reg .u64 t; cvta.to.shared.u64 t, %1; cvt.u32.u64 %0, t; }" : "=r"(a) : "l"(p));
    return a;
}
__device__ __forceinline__ void cp_async16(uint32_t dst, const void* src) {
    asm volatile("cp.async.cg.shared.global [%0], [%1], 16;" :: "r"(dst), "l"(src));
}
__device__ __forceinline__ void ldsm_x4(uint32_t& r0, uint32_t& r1, uint32_t& r2, uint32_t& r3,
                                        uint32_t addr) {
    asm volatile("ldmatrix.sync.aligned.m8n8.x4.shared.b16 {%0,%1,%2,%3}, [%4];"
                 : "=r"(r0), "=r"(r1), "=r"(r2), "=r"(r3) : "r"(addr));
}
__device__ __forceinline__ void mma_f16(float* c, const uint32_t* a, const uint32_t* b) {
    asm volatile("mma.sync.aligned.m16n8k16.row.col.f32.f16.f16.f32 "
                 "{%0,%1,%2,%3}, {%4,%5,%6,%7}, {%8,%9}, {%0,%1,%2,%3};"
                 : "+f"(c[0]), "+f"(c[1]), "+f"(c[2]), "+f"(c[3])
                 : "r"(a[0]), "r"(a[1]), "r"(a[2]), "r"(a[3]), "r"(b[0]), "r"(b[1]));
}

// ---------------- merged preprocessing ----------------
#define N_VOC ((long long)VV*HH)
#define N_W0  (HH*EE)
#define N_W1  (HH*HH)
#define N_WQ  (3*HH*HH)
#define N_WO  (HH*HH)
#define N_EMB (MM*EE)
#define N_PREP (N_VOC + N_W0 + N_W1 + N_WQ + N_WO + N_EMB)

__global__ void prep_kernel(const float* __restrict__ out_w,
                            const float* __restrict__ W0,
                            const float* __restrict__ W1,
                            const float* __restrict__ Wq,
                            const float* __restrict__ Wo,
                            const int* __restrict__ x,
                            const float* __restrict__ emb) {
    long long idx = (long long)blockIdx.x * blockDim.x + threadIdx.x;
    if (idx < 32*1024) g_l[idx] = 0.f;     // zero attention row sums every run
    if (idx < N_VOC) { g_Bh[idx] = __float2half(out_w[idx]); return; }
    idx -= N_VOC;
    if (idx < N_W0) { g_W0h[idx] = __float2half(W0[idx]); return; }
    idx -= N_W0;
    if (idx < N_W1) { g_W1h[idx] = __float2half(W1[idx]); return; }
    idx -= N_W1;
    if (idx < N_WQ) { g_Wqh[idx] = __float2half(Wq[idx]); return; }
    idx -= N_WQ;
    if (idx < N_WO) { g_Woh[idx] = __float2half(Wo[idx]); return; }
    idx -= N_WO;
    if (idx >= N_EMB) return;
    int i = (int)idx;
    int m = i >> 9;
    int e = i & 511;
    int s = m & (SS - 1);
    int tok = x[m];
    int i2 = e & ~1;
    float freq = expf((float)i2 * (-9.210340371976184f / 512.0f));
    float ang = (float)s * freq;
    float pe = (e & 1) ? cosf(ang) : sinf(ang);
    float v = emb[(size_t)tok * EE + e] + pe;
    __half h = __float2half(v);
    g_Ahi[i] = h;
    g_Alo[i] = __float2half(v - __half2float(h));
}

// ============== dedicated vocab GEMM: C[4096,32000] = A[4096,512]@B[32000,512]^T + bias ==============
// fp16 single product, fixed sizes, BK=64 (8 stages), 128x128 tile, 8 warps 2x4.
#define VSPAD 72
#define VTILE (128*VSPAD)           // halves per tile
#define GV_SMEM (2*2*VTILE*2)       // 73728 bytes

__global__ __launch_bounds__(256, 2) void gemm_vocab(
    const __half* __restrict__ A_, const __half* __restrict__ B_,
    const float* __restrict__ bias, float* __restrict__ C)
{
    extern __shared__ __align__(16) __half smh[];
    const uint32_t smb = smem_u32(smh);
    const int tid = threadIdx.x;
    const int lane = tid & 31;
    const int wid = tid >> 5;
    const int warp_m = wid >> 2;      // 0..1
    const int warp_n = wid & 3;       // 0..3
    const int bm = blockIdx.y * 128;
    const int bn = blockIdx.x * 128;

    const __half* pA = A_ + (size_t)bm * 512;
    const __half* pB = B_ + (size_t)bn * 512;

    float acc[4][4][4];
    #pragma unroll
    for (int i = 0; i < 4; i++)
        #pragma unroll
        for (int j = 0; j < 4; j++)
            #pragma unroll
            for (int r = 0; r < 4; r++) acc[i][j][r] = 0.f;

    const int lrow = tid >> 3;        // 0..31
    const int lcol = (tid & 7) * 8;   // 0..56

    auto prefetch = [&](int s) {
        const int gk = s * 64;
        const uint32_t base = smb + (uint32_t)((s & 1) * 2 * VTILE) * 2;
        #pragma unroll
        for (int c = 0; c < 4; c++) {
            int row = lrow + c * 32;
            cp_async16(base + (uint32_t)(row * VSPAD + lcol) * 2,
                       pA + (size_t)row * 512 + gk + lcol);
            cp_async16(base + (uint32_t)(VTILE + row * VSPAD + lcol) * 2,
                       pB + (size_t)row * 512 + gk + lcol);
        }
    };

    prefetch(0);
    asm volatile("cp.async.commit_group;");

    #pragma unroll 1
    for (int s = 0; s < 8; s++) {
        if (s < 7) {
            prefetch(s + 1);
            asm volatile("cp.async.commit_group;");
            asm volatile("cp.async.wait_group 1;");
        } else {
            asm volatile("cp.async.wait_group 0;");
        }
        __syncthreads();

        const uint32_t stg = smb + (uint32_t)((s & 1) * 2 * VTILE) * 2;
        const uint32_t tA = stg;
        const uint32_t tB = stg + VTILE * 2;
        const int q  = lane >> 3;
        const int rr = lane & 7;

        #pragma unroll
        for (int ko = 0; ko < 64; ko += 16) {
            const int arow = warp_m * 64 + (q & 1) * 8 + rr;
            const int acol = ko + (q >> 1) * 8;
            const int brow = warp_n * 32 + (q >> 1) * 8 + rr;
            const int bcol = ko + (q & 1) * 8;

            uint32_t b[4][2];
            #pragma unroll
            for (int j = 0; j < 2; j++)
                ldsm_x4(b[2*j][0], b[2*j][1], b[2*j+1][0], b[2*j+1][1],
                        tB + (uint32_t)((brow + j * 16) * VSPAD + bcol) * 2);
            uint32_t a[4][4];
            #pragma unroll
            for (int i = 0; i < 4; i++)
                ldsm_x4(a[i][0], a[i][1], a[i][2], a[i][3],
                        tA + (uint32_t)((arow + i * 16) * VSPAD + acol) * 2);
            #pragma unroll
            for (int i = 0; i < 4; i++)
                #pragma unroll
                for (int j = 0; j < 4; j++)
                    mma_f16(acc[i][j], a[i], b[j]);
        }
        __syncthreads();
    }

    const int gr = lane >> 2;
    const int gc = (lane & 3) * 2;
    #pragma unroll
    for (int j = 0; j < 4; j++) {
        int col = bn + warp_n * 32 + j * 8 + gc;
        float2 bv = *(const float2*)(bias + col);
        #pragma unroll
        for (int i = 0; i < 4; i++) {
            int row0 = bm + warp_m * 64 + i * 16 + gr;
            *(float2*)(C + (size_t)row0 * VV + col) =
                make_float2(acc[i][j][0] + bv.x, acc[i][j][1] + bv.y);
            *(float2*)(C + (size_t)(row0 + 8) * VV + col) =
                make_float2(acc[i][j][2] + bv.x, acc[i][j][3] + bv.y);
        }
    }
}

// ============== generic fp16 NT GEMM, 1- or 2-term A ==============
#define SPAD 40
#define TILE_E (128*SPAD)
#define GF_SMEM (2*3*TILE_E*2)    // 61440 bytes

__global__ __launch_bounds__(256, 2) void gemm_f16_mma(
    const __half* __restrict__ Ahi_, const __half* __restrict__ Alo_,
    const __half* __restrict__ B_,
    const float* __restrict__ bias, float* __restrict__ C_,
    __half* __restrict__ Chi_, __half* __restrict__ Clo_,
    __half* __restrict__ Fh_,
    float* __restrict__ Lsum_, const float* __restrict__ Ldiv_,
    long long ls1, long long ls2, int qkvmode,
    int K, int lda, int ldb, int ldc, int nValid, float scale,
    int zmod, long long sA1, long long sA2, long long sB1, long long sB2,
    long long sC1, long long sC2)
{
    extern __shared__ __align__(16) __half smh[];
    const uint32_t smb = smem_u32(smh);

    const int tid = threadIdx.x;
    const int lane = tid & 31;
    const int wid = tid >> 5;
    const int warp_m = wid >> 2;
    const int warp_n = wid & 3;
    const int bm = blockIdx.y * 128;
    const int bn = blockIdx.x * 128;
    const bool two = (Alo_ != nullptr);

    const int z = blockIdx.z;
    const int z1 = z % zmod, z2 = z / zmod;
    const long long offA = (long long)z1 * sA1 + (long long)z2 * sA2;
    const long long offB = (long long)z1 * sB1 + (long long)z2 * sB2;
    const long long offC = (long long)z1 * sC1 + (long long)z2 * sC2;
    const long long lbase = (long long)z1 * ls1 + (long long)z2 * ls2;

    const __half* pT[3] = { Ahi_ + offA + (size_t)bm * lda,
                            two ? (Alo_ + offA + (size_t)bm * lda) : nullptr,
                            B_   + offB + (size_t)bn * ldb };

    float acc[4][4][4];
    #pragma unroll
    for (int i = 0; i < 4; i++)
        #pragma unroll
        for (int j = 0; j < 4; j++)
            #pragma unroll
            for (int r = 0; r < 4; r++) acc[i][j][r] = 0.f;

    const int lrow = tid >> 2;
    const int lcol = (tid & 3) * 8;
    const int nstages = K >> 5;

    auto prefetch = [&](int s) {
        const int gk = s * 32;
        const uint32_t base = smb + (uint32_t)((s & 1) * 3 * TILE_E) * 2;
        #pragma unroll
        for (int t = 0; t < 3; t++) {
            if (t == 1 && !two) continue;
            const __half* src = pT[t] + gk + lcol;
            const int ld = (t < 2) ? lda : ldb;
            #pragma unroll
            for (int c = 0; c < 2; c++) {
                int row = lrow + c * 64;
                cp_async16(base + (uint32_t)(t * TILE_E + row * SPAD + lcol) * 2,
                           src + (size_t)row * ld);
            }
        }
    };

    prefetch(0);
    asm volatile("cp.async.commit_group;");

    for (int s = 0; s < nstages; s++) {
        if (s < nstages - 1) {
            prefetch(s + 1);
            asm volatile("cp.async.commit_group;");
            asm volatile("cp.async.wait_group 1;");
        } else {
            asm volatile("cp.async.wait_group 0;");
        }
        __syncthreads();

        const uint32_t stg = smb + (uint32_t)((s & 1) * 3 * TILE_E) * 2;
        const uint32_t tAhi = stg;
        const uint32_t tAlo = stg + TILE_E * 2;
        const uint32_t tB   = stg + 2 * TILE_E * 2;
        const int q  = lane >> 3;
        const int rr = lane & 7;

        #pragma unroll
        for (int ko = 0; ko < 32; ko += 16) {
            const int arow = warp_m * 64 + (q & 1) * 8 + rr;
            const int acol = ko + (q >> 1) * 8;
            const int brow = warp_n * 32 + (q >> 1) * 8 + rr;
            const int bcol = ko + (q & 1) * 8;

            uint32_t b[4][2];
            #pragma unroll
            for (int j = 0; j < 2; j++)
                ldsm_x4(b[2*j][0], b[2*j][1], b[2*j+1][0], b[2*j+1][1],
                        tB + (uint32_t)((brow + j * 16) * SPAD + bcol) * 2);
            uint32_t aH[4][4];
            #pragma unroll
            for (int i = 0; i < 4; i++)
                ldsm_x4(aH[i][0], aH[i][1], aH[i][2], aH[i][3],
                        tAhi + (uint32_t)((arow + i * 16) * SPAD + acol) * 2);
            #pragma unroll
            for (int i = 0; i < 4; i++)
                #pragma unroll
                for (int j = 0; j < 4; j++)
                    mma_f16(acc[i][j], aH[i], b[j]);
            if (two) {
                uint32_t aL[4][4];
                #pragma unroll
                for (int i = 0; i < 4; i++)
                    ldsm_x4(aL[i][0], aL[i][1], aL[i][2], aL[i][3],
                            tAlo + (uint32_t)((arow + i * 16) * SPAD + acol) * 2);
                #pragma unroll
                for (int i = 0; i < 4; i++)
                    #pragma unroll
                    for (int j = 0; j < 4; j++)
                        mma_f16(acc[i][j], aL[i], b[j]);
            }
        }
        __syncthreads();
    }

    const int gr = lane >> 2;
    const int gc = (lane & 3) * 2;

    if (qkvmode) {
        __half* Qd = Chi_;
        __half* Kd = Clo_;
        __half* Vd = Fh_;
        #pragma unroll
        for (int j = 0; j < 4; j++) {
            int col = bn + warp_n * 32 + j * 8 + gc;
            float2 bv = *(const float2*)(bias + col);
            #pragma unroll
            for (int i = 0; i < 4; i++) {
                int row0 = bm + warp_m * 64 + i * 16 + gr;
                float v00 = acc[i][j][0] + bv.x, v01 = acc[i][j][1] + bv.y;
                float v10 = acc[i][j][2] + bv.x, v11 = acc[i][j][3] + bv.y;
                int b0 = row0 >> 10, s0 = row0 & 1023;
                if (col < 1024) {
                    __half* D = (col < 512) ? Qd : Kd;
                    int c = (col < 512) ? col : col - 512;
                    int hd = c >> 6, d = c & 63;
                    size_t o0 = ((size_t)((b0*8 + hd) * 1024 + s0)) * 64 + d;
                    *(__half2*)(D + o0)           = __floats2half2_rn(v00, v01);
                    *(__half2*)(D + o0 + 8*64)    = __floats2half2_rn(v10, v11);
                } else {
                    int c = col - 1024;
                    int hd = c >> 6, d = c & 63;
                    size_t base = (size_t)(b0*8 + hd) * 131072;
                    Vd[base + (size_t)d*1024     + s0]     = __float2half(v00);
                    Vd[base + (size_t)(d+1)*1024 + s0]     = __float2half(v01);
                    Vd[base + (size_t)d*1024     + s0 + 8] = __float2half(v10);
                    Vd[base + (size_t)(d+1)*1024 + s0 + 8] = __float2half(v11);
                }
            }
        }
        return;
    }

    if (Lsum_) {
        __half* Fh = Fh_ + offC;
        float rs[4][2];
        #pragma unroll
        for (int i = 0; i < 4; i++) { rs[i][0] = 0.f; rs[i][1] = 0.f; }
        #pragma unroll
        for (int j = 0; j < 4; j++) {
            int col = bn + warp_n * 32 + j * 8 + gc;
            #pragma unroll
            for (int i = 0; i < 4; i++) {
                int row0 = bm + warp_m * 64 + i * 16 + gr;
                float e00 = __expf(fminf(acc[i][j][0]*scale, 10.5f));
                float e01 = __expf(fminf(acc[i][j][1]*scale, 10.5f));
                float e10 = __expf(fminf(acc[i][j][2]*scale, 10.5f));
                float e11 = __expf(fminf(acc[i][j][3]*scale, 10.5f));
                *(__half2*)(Fh + (size_t)row0 * ldc + col)       = __floats2half2_rn(e00, e01);
                *(__half2*)(Fh + (size_t)(row0 + 8) * ldc + col) = __floats2half2_rn(e10, e11);
                rs[i][0] += e00 + e01;
                rs[i][1] += e10 + e11;
            }
        }
        #pragma unroll
        for (int i = 0; i < 4; i++)
            #pragma unroll
            for (int hh = 0; hh < 2; hh++) {
                float v = rs[i][hh];
                v += __shfl_xor_sync(0xffffffffu, v, 1);
                v += __shfl_xor_sync(0xffffffffu, v, 2);
                rs[i][hh] = v;
            }
        if ((lane & 3) == 0) {
            #pragma unroll
            for (int i = 0; i < 4; i++) {
                int row0 = bm + warp_m * 64 + i * 16 + gr;
                atomicAdd(Lsum_ + lbase + row0,     rs[i][0]);
                atomicAdd(Lsum_ + lbase + row0 + 8, rs[i][1]);
            }
        }
        return;
    }

    float* C = C_ ? C_ + offC : nullptr;
    __half* Chi = Chi_ ? Chi_ + offC : nullptr;
    __half* Clo = Clo_ ? Clo_ + offC : nullptr;
    __half* Fh = Fh_ ? Fh_ + offC : nullptr;

    #pragma unroll
    for (int j = 0; j < 4; j++) {
        int col = bn + warp_n * 32 + j * 8 + gc;
        if (col >= nValid) continue;
        float2 bv = make_float2(0.f, 0.f);
        if (bias) bv = *(const float2*)(bias + col);
        #pragma unroll
        for (int i = 0; i < 4; i++) {
            int row0 = bm + warp_m * 64 + i * 16 + gr;
            float s0 = scale, s1 = scale;
            if (Ldiv_) {
                s0 = scale / Ldiv_[lbase + row0];
                s1 = scale / Ldiv_[lbase + row0 + 8];
            }
            float v00 = acc[i][j][0]*s0 + bv.x, v01 = acc[i][j][1]*s0 + bv.y;
            float v10 = acc[i][j][2]*s1 + bv.x, v11 = acc[i][j][3]*s1 + bv.y;
            size_t o0 = (size_t)row0 * ldc + col;
            size_t o1 = (size_t)(row0 + 8) * ldc + col;
            if (Chi) {
                __half h;
                h = __float2half(v00); Chi[o0]   = h; Clo[o0]   = __float2half(v00 - __half2float(h));
                h = __float2half(v01); Chi[o0+1] = h; Clo[o0+1] = __float2half(v01 - __half2float(h));
                h = __float2half(v10); Chi[o1]   = h; Clo[o1]   = __float2half(v10 - __half2float(h));
                h = __float2half(v11); Chi[o1+1] = h; Clo[o1+1] = __float2half(v11 - __half2float(h));
            } else if (Fh) {
                *(__half2*)(Fh + o0) = __floats2half2_rn(v00, v01);
                *(__half2*)(Fh + o1) = __floats2half2_rn(v10, v11);
            } else {
                *(float2*)(C + o0) = make_float2(v00, v01);
                *(float2*)(C + o1) = make_float2(v10, v11);
            }
        }
    }
}

// ---------------- parallel liquid scan (exact affine chunk decomposition) ----------------
__global__ __launch_bounds__(512) void liquid_scan_par(
    const float* __restrict__ I, const float* __restrict__ tau,
    const float* __restrict__ log_dt, float* __restrict__ out) {
    const int b = blockIdx.x;
    const int lg = blockIdx.y;
    const int lane16 = threadIdx.x & 15;
    const int chunk  = threadIdx.x >> 4;
    const int o = lg * 16 + lane16;
    const float dt = expf(log_dt[0]);
    const float r = dt / tau[o];
    const float a = 1.f - r;
    const float* Ib = I + (size_t)b * SS * HH + o;
    const int t0 = chunk * 32;

    float Iv[32];
    #pragma unroll
    for (int i = 0; i < 32; i++) Iv[i] = Ib[(size_t)(t0 + i) * HH];

    float u = 0.f, s = 0.f;
    #pragma unroll
    for (int i = 0; i < 32; i++) {
        float sn = s + r * (u - s);
        u = u + r * (Iv[i] - u);
        s = sn;
    }
    __shared__ float2 dloc[32][16];
    __shared__ float2 st[32][16];
    dloc[chunk][lane16] = make_float2(u, s);
    __syncthreads();

    if (chunk == 0) {
        float a2 = a*a, a4 = a2*a2, a8 = a4*a4, a16 = a8*a8;
        float a32v = a16*a16;
        float a31 = a16*a8*a4*a2*a;
        float c32 = 32.f * r * a31;
        float2 x = make_float2(0.f, 0.f);
        #pragma unroll
        for (int c = 0; c < 32; c++) {
            st[c][lane16] = x;
            float2 d = dloc[c][lane16];
            float nu = a32v * x.x + d.x;
            float ns = c32 * x.x + a32v * x.y + d.y;
            x = make_float2(nu, ns);
        }
    }
    __syncthreads();

    float2 x0 = st[chunk][lane16];
    u = x0.x; s = x0.y;
    float* Ob = out + (size_t)b * SS * HH + o;
    #pragma unroll
    for (int i = 0; i < 32; i++) {
        float sn = s + r * (u - s);
        u = u + r * (Iv[i] - u);
        s = sn;
        Ob[(size_t)(t0 + i) * HH] = tanhf(s);
    }
}

// ---------------- layernorm -> fp16 hi/lo ----------------
__global__ void layernorm_split(const float* __restrict__ in, const float* __restrict__ g,
                                const float* __restrict__ be,
                                __half* __restrict__ hi, __half* __restrict__ lo) {
    int row = blockIdx.x;
    int tid = threadIdx.x;
    const float* p = in + (size_t)row * HH;
    float a = p[tid], b = p[tid + 256];
    float sum = a + b, sq = a*a + b*b;
    __shared__ float s1[8], s2[8];
    #pragma unroll
    for (int o = 16; o; o >>= 1) {
        sum += __shfl_xor_sync(0xffffffffu, sum, o);
        sq  += __shfl_xor_sync(0xffffffffu, sq,  o);
    }
    if ((tid & 31) == 0) { s1[tid>>5] = sum; s2[tid>>5] = sq; }
    __syncthreads();
    sum = 0.f; sq = 0.f;
    #pragma unroll
    for (int i = 0; i < 8; i++) { sum += s1[i]; sq += s2[i]; }
    float mean = sum * (1.f/512.f);
    float var  = sq * (1.f/512.f) - mean*mean;
    float inv = rsqrtf(var + 1e-5f);
    float y0 = (a - mean) * inv * g[tid]       + be[tid];
    float y1 = (b - mean) * inv * g[tid + 256] + be[tid + 256];
    size_t base = (size_t)row * HH;
    __half h0 = __float2half(y0);
    __half h1 = __float2half(y1);
    hi[base + tid]       = h0;
    hi[base + tid + 256] = h1;
    lo[base + tid]       = __float2half(y0 - __half2float(h0));
    lo[base + tid + 256] = __float2half(y1 - __half2float(h1));
}

// ---------------- host orchestration ----------------
extern "C" void kernel_launch(void* const* d_in, const int* in_sizes, int n_in,
                              void* d_out, int out_size) {
    const int*   x          = (const int*)  d_in[0];
    const float* emb        = (const float*)d_in[1];
    const float* W0         = (const float*)d_in[2];
    const float* b0         = (const float*)d_in[3];
    const float* tau0       = (const float*)d_in[4];
    const float* g0         = (const float*)d_in[5];
    const float* be0        = (const float*)d_in[6];
    const float* W1         = (const float*)d_in[7];
    const float* b1         = (const float*)d_in[8];
    const float* tau1       = (const float*)d_in[9];
    const float* g1         = (const float*)d_in[10];
    const float* be1        = (const float*)d_in[11];
    const float* attn_in_w  = (const float*)d_in[12];
    const float* attn_in_b  = (const float*)d_in[13];
    const float* attn_out_w = (const float*)d_in[14];
    const float* attn_out_b = (const float*)d_in[15];
    const float* out_w      = (const float*)d_in[16];
    const float* out_b      = (const float*)d_in[17];
    const float* log_dt     = (const float*)d_in[18];
    float* out = (float*)d_out;

    float *I, *sbuf, *lsum;
    __half *Ahi, *Alo, *A2hi, *A2lo, *H2;
    __half *W0h, *W1h, *Wqh, *Woh, *Bh, *Qh, *Kh, *Vth, *Sh;
    cudaGetSymbolAddress((void**)&I,      g_I);
    cudaGetSymbolAddress((void**)&sbuf,   g_s);
    cudaGetSymbolAddress((void**)&lsum,   g_l);
    cudaGetSymbolAddress((void**)&Ahi,    g_Ahi);
    cudaGetSymbolAddress((void**)&Alo,    g_Alo);
    cudaGetSymbolAddress((void**)&A2hi,   g_A2hi);
    cudaGetSymbolAddress((void**)&A2lo,   g_A2lo);
    cudaGetSymbolAddress((void**)&H2,     g_H2);
    cudaGetSymbolAddress((void**)&Bh,     g_Bh);
    cudaGetSymbolAddress((void**)&W0h,    g_W0h);
    cudaGetSymbolAddress((void**)&W1h,    g_W1h);
    cudaGetSymbolAddress((void**)&Wqh,    g_Wqh);
    cudaGetSymbolAddress((void**)&Woh,    g_Woh);
    cudaGetSymbolAddress((void**)&Qh,     g_Qh);
    cudaGetSymbolAddress((void**)&Kh,     g_Kh);
    cudaGetSymbolAddress((void**)&Vth,    g_Vth);
    cudaGetSymbolAddress((void**)&Sh,     g_Sh);

    cudaFuncSetAttribute(gemm_f16_mma,
                         cudaFuncAttributeMaxDynamicSharedMemorySize, GF_SMEM);
    cudaFuncSetAttribute(gemm_vocab,
                         cudaFuncAttributeMaxDynamicSharedMemorySize, GV_SMEM);

    // merged preprocessing (also zeroes g_l)
    prep_kernel<<<(unsigned)((N_PREP + 255)/256), 256>>>(out_w, W0, W1, attn_in_w, attn_out_w, x, emb);

    // 2. liquid layer 0 (fp16: exact A hi/lo x rounded W)
    gemm_f16_mma<<<dim3(4, 32, 1), 256, GF_SMEM>>>(
        Ahi, Alo, W0h, b0, I, nullptr, nullptr, nullptr, nullptr, nullptr, 0, 0, 0,
        EE, EE, EE, HH, HH, 1.f, 1, 0,0,0,0,0,0);
    liquid_scan_par<<<dim3(BB, 32), 512>>>(I, tau0, log_dt, sbuf);
    layernorm_split<<<MM, 256>>>(sbuf, g0, be0, Ahi, Alo);

    // 3. liquid layer 1
    gemm_f16_mma<<<dim3(4, 32, 1), 256, GF_SMEM>>>(
        Ahi, Alo, W1h, b1, I, nullptr, nullptr, nullptr, nullptr, nullptr, 0, 0, 0,
        HH, HH, HH, HH, HH, 1.f, 1, 0,0,0,0,0,0);
    liquid_scan_par<<<dim3(BB, 32), 512>>>(I, tau1, log_dt, sbuf);
    layernorm_split<<<MM, 256>>>(sbuf, g1, be1, Ahi, Alo);

    // 4. MHA: qkv projection with fused Q/K/V scatter epilogue
    gemm_f16_mma<<<dim3(12, 32, 1), 256, GF_SMEM>>>(
        Ahi, Alo, Wqh, attn_in_b, nullptr, Qh, Kh, Vth, nullptr, nullptr, 0, 0, 1,
        HH, HH, HH, 3*HH, 3*HH, 1.f, 1, 0,0,0,0,0,0);

    // scores + fused exp + row-sum atomics: P~ = exp(QK^T/8) -> Sh, sums -> g_l
    gemm_f16_mma<<<dim3(8, 8, 32), 256, GF_SMEM>>>(
        Qh, nullptr, Kh, nullptr, nullptr, nullptr, nullptr, Sh, lsum, nullptr, 1024, 0, 0,
        64, 64, 64, 1024, 1024, 0.125f,
        32, 65536LL, 0, 65536LL, 0, 1LL<<20, 0);

    // AV = P~ @ Vt^T with fused 1/l normalization -> fp16 hi/lo A2
    gemm_f16_mma<<<dim3(1, 8, 32), 256, GF_SMEM>>>(
        Sh, nullptr, Vth, nullptr, nullptr, A2hi, A2lo, nullptr, nullptr, lsum, 1024, 8192, 0,
        1024, 1024, 1024, 512, 64, 1.f,
        8, 1LL<<20, 8LL<<20, 131072LL, 8LL*131072, 64LL, 524288LL);

    // out-projection (fp16 2-term A) -> single fp16 H2
    gemm_f16_mma<<<dim3(4, 32, 1), 256, GF_SMEM>>>(
        A2hi, A2lo, Woh, attn_out_b, nullptr, nullptr, nullptr, H2, nullptr, nullptr, 0, 0, 0,
        HH, HH, HH, HH, HH, 1.f, 1, 0,0,0,0,0,0);

    // 5. vocab projection (dedicated fixed-size kernel, BK=64)
    gemm_vocab<<<dim3(VV/128, MM/128), 256, GV_SMEM>>>(H2, Bh, out_b, out);
}